// round 9
// baseline (speedup 1.0000x reference)
#include <cuda_runtime.h>
#include <cuda_bf16.h>
#include <cstdint>

#define NPTS 4096
#define CH   512
#define OUTF 256
#define EPSV 1e-5f
#define SK   24    // smem k-stride (bf16) for 16-wide k-slices: 48B rows, cp.async-aligned, conflict-free
#define NKIT (CH / 16)   // 32 k-iterations of 16

// ---------------- scratch (device-side only) ----------------
__device__ __nv_bfloat16 g_sib[(size_t)NPTS * NPTS];
__device__ float g_u [(size_t)NPTS * CH];
__device__ float g_v [(size_t)NPTS * CH];
__device__ float g_dinv[NPTS];
__device__ int   g_deg [NPTS];
__device__ int   g_idx [NPTS * 16];
__device__ __nv_bfloat16 g_xh[(size_t)NPTS * CH], g_xl[(size_t)NPTS * CH];
__device__ __nv_bfloat16 g_uwh[CH * CH],  g_uwl[CH * CH];
__device__ __nv_bfloat16 g_vwh[CH * CH],  g_vwl[CH * CH];
__device__ __nv_bfloat16 g_fwh[OUTF * CH], g_fwl[OUTF * CH];
__device__ __nv_bfloat16 g_hh[(size_t)NPTS * CH], g_hl[(size_t)NPTS * CH];

__device__ __forceinline__ void mma16816(float c[4], const uint32_t a[4], const uint32_t b[2])
{
    asm volatile(
        "mma.sync.aligned.m16n8k16.row.col.f32.bf16.bf16.f32 "
        "{%0,%1,%2,%3}, {%4,%5,%6,%7}, {%8,%9}, {%0,%1,%2,%3};"
        : "+f"(c[0]), "+f"(c[1]), "+f"(c[2]), "+f"(c[3])
        : "r"(a[0]), "r"(a[1]), "r"(a[2]), "r"(a[3]), "r"(b[0]), "r"(b[1]));
}

__device__ __forceinline__ void ldsm_x4(uint32_t r[4], uint32_t saddr)
{
    asm volatile("ldmatrix.sync.aligned.m8n8.x4.shared.b16 {%0,%1,%2,%3}, [%4];"
                 : "=r"(r[0]), "=r"(r[1]), "=r"(r[2]), "=r"(r[3]) : "r"(saddr));
}

__device__ __forceinline__ void cpa16(uint32_t dst, const void* src)
{
    asm volatile("cp.async.cg.shared.global [%0], [%1], 16;" :: "r"(dst), "l"(src));
}
__device__ __forceinline__ void cpa_commit() { asm volatile("cp.async.commit_group;"); }
__device__ __forceinline__ void cpa_wait1()  { asm volatile("cp.async.wait_group 1;"); }
__device__ __forceinline__ void cpa_wait0()  { asm volatile("cp.async.wait_group 0;"); }

// ================= K0: one-shot hi/lo bf16 split of x, Uw, Vw, fc_w =================
__global__ __launch_bounds__(256) void split_kernel(const float* __restrict__ X,
                                                    const float* __restrict__ Uw,
                                                    const float* __restrict__ Vw,
                                                    const float* __restrict__ Fw)
{
    size_t i = (size_t)blockIdx.x * 256 + threadIdx.x;
    const float* src; __nv_bfloat16 *dh, *dl; size_t off;
    if (i < 524288)      { src = X;  dh = g_xh;  dl = g_xl;  off = i; }
    else if (i < 589824) { src = Uw; dh = g_uwh; dl = g_uwl; off = i - 524288; }
    else if (i < 655360) { src = Vw; dh = g_vwh; dl = g_vwl; off = i - 589824; }
    else                 { src = Fw; dh = g_fwh; dl = g_fwl; off = i - 655360; }

    float4 v = ((const float4*)src)[off];
    float f[4] = {v.x, v.y, v.z, v.w};
    uint32_t hw[2], lw[2];
#pragma unroll
    for (int p = 0; p < 2; p++) {
        __nv_bfloat16 h0 = __float2bfloat16_rn(f[p * 2]);
        __nv_bfloat16 h1 = __float2bfloat16_rn(f[p * 2 + 1]);
        __nv_bfloat162 hp; hp.x = h0; hp.y = h1;
        __nv_bfloat162 lp = __floats2bfloat162_rn(f[p * 2] - __bfloat162float(h0),
                                                  f[p * 2 + 1] - __bfloat162float(h1));
        hw[p] = *(uint32_t*)&hp;
        lw[p] = *(uint32_t*)&lp;
    }
    *(uint2*)&dh[off * 4] = make_uint2(hw[0], hw[1]);
    *(uint2*)&dl[off * 4] = make_uint2(lw[0], lw[1]);
}

// ===== K1: si = xh@xh.T, upper-tri + smem-transposed mirror; cp.async 2-stage =====
// smem: stage st at [st*12288, st*12288+12288): As 6144 B then Bs 6144 B. Ts aliases all.
__global__ __launch_bounds__(256, 2) void si_mma()
{
    const int bj = blockIdx.x, bi = blockIdx.y;
    if (bi > bj) return;
    const int m0 = bi * 128, n0 = bj * 128;

    __shared__ __align__(16) unsigned char sraw[34816];
    __nv_bfloat16* Ts = reinterpret_cast<__nv_bfloat16*>(sraw);
    const uint32_t S_u = (uint32_t)__cvta_generic_to_shared(sraw);

    const int tid  = threadIdx.x;
    const int warp = tid >> 5, lane = tid & 31;
    const int wm = warp & 3, wn = warp >> 2;
    const int grp = lane >> 2, qd = lane & 3;
    const int l7 = lane & 7;

    const uint32_t a_off = ((wm * 32 + ((lane >> 3) & 1) * 8 + l7) * SK + ((lane >> 4) & 1) * 8) * 2;
    const uint32_t b_off = ((wn * 64 + ((lane >> 4) & 1) * 8 + l7) * SK + ((lane >> 3) & 1) * 8) * 2;

    float acc[2][8][4];
#pragma unroll
    for (int mi = 0; mi < 2; mi++)
#pragma unroll
        for (int ni = 0; ni < 8; ni++)
#pragma unroll
            for (int e = 0; e < 4; e++) acc[mi][ni][e] = 0.f;

    const int rr = tid >> 1;
    const int sg = (tid & 1) * 8;
    const uint32_t soff = (uint32_t)(rr * SK + sg) * 2;

    // prologue: stage 0
    {
        uint32_t b = S_u + soff;
        cpa16(b,        &g_xh[(size_t)(m0 + rr) * CH + sg]);
        cpa16(b + 6144, &g_xh[(size_t)(n0 + rr) * CH + sg]);
        cpa_commit();
    }

    for (int k = 0; k < NKIT; k++) {
        const int cur = k & 1;
        if (k + 1 < NKIT) {
            uint32_t b = S_u + (cur ^ 1) * 12288 + soff;
            int k0 = (k + 1) * 16;
            cpa16(b,        &g_xh[(size_t)(m0 + rr) * CH + k0 + sg]);
            cpa16(b + 6144, &g_xh[(size_t)(n0 + rr) * CH + k0 + sg]);
            cpa_commit();
            cpa_wait1();
        } else {
            cpa_wait0();
        }
        __syncthreads();

        const uint32_t base = S_u + cur * 12288;
        uint32_t afr[2][4];
        ldsm_x4(afr[0], base + a_off);
        ldsm_x4(afr[1], base + a_off + 16 * SK * 2);
#pragma unroll
        for (int ni = 0; ni < 8; ni += 2) {
            uint32_t b4[4];
            ldsm_x4(b4, base + 6144 + b_off + ni * 8 * SK * 2);
#pragma unroll
            for (int mi = 0; mi < 2; mi++) {
                mma16816(acc[mi][ni],     afr[mi], &b4[0]);
                mma16816(acc[mi][ni + 1], afr[mi], &b4[2]);
            }
        }
        __syncthreads();
    }

#pragma unroll
    for (int mi = 0; mi < 2; mi++) {
        int m = m0 + wm * 32 + mi * 16 + grp;
#pragma unroll
        for (int ni = 0; ni < 8; ni++) {
            int n = n0 + wn * 64 + ni * 8 + qd * 2;
            *(__nv_bfloat162*)&g_sib[(size_t)m * NPTS + n] =
                __floats2bfloat162_rn(acc[mi][ni][0], acc[mi][ni][1]);
            *(__nv_bfloat162*)&g_sib[(size_t)(m + 8) * NPTS + n] =
                __floats2bfloat162_rn(acc[mi][ni][2], acc[mi][ni][3]);
        }
    }

    if (bi != bj) {
#pragma unroll
        for (int mi = 0; mi < 2; mi++) {
            int ml = wm * 32 + mi * 16 + grp;
#pragma unroll
            for (int ni = 0; ni < 8; ni++) {
                int nl = wn * 64 + ni * 8 + qd * 2;
                Ts[nl * 136 + ml]           = __float2bfloat16_rn(acc[mi][ni][0]);
                Ts[(nl + 1) * 136 + ml]     = __float2bfloat16_rn(acc[mi][ni][1]);
                Ts[nl * 136 + ml + 8]       = __float2bfloat16_rn(acc[mi][ni][2]);
                Ts[(nl + 1) * 136 + ml + 8] = __float2bfloat16_rn(acc[mi][ni][3]);
            }
        }
        __syncthreads();
        const int r = tid >> 1, hh = (tid & 1) * 64;
#pragma unroll
        for (int i = 0; i < 8; i++) {
            *(uint4*)&g_sib[(size_t)(n0 + r) * NPTS + m0 + hh + i * 8] =
                *(const uint4*)&Ts[r * 136 + hh + i * 8];
        }
    }
}

// ================= K2: approx top-8 candidates + fp32 exact refine =================
__device__ __forceinline__ void ins8(float v[8], float x)
{
    if (x > v[7]) {
        v[7] = x;
#pragma unroll
        for (int i = 7; i > 0; i--) {
            if (v[i] > v[i - 1]) { float t = v[i]; v[i] = v[i - 1]; v[i - 1] = t; }
        }
    }
}

__global__ __launch_bounds__(256) void topk_refine(const float* __restrict__ X)
{
    const int row = blockIdx.x;
    const int tid = threadIdx.x;
    const int warp = tid >> 5, lane = tid & 31;
    const uint4* __restrict__ s4 = (const uint4*)(g_sib + (size_t)row * NPTS);

    __shared__ float sv[256][8];
    __shared__ float xr[CH];
    __shared__ float ex[32];
    __shared__ int   cand[32];
    __shared__ int   cnt;
    __shared__ float thr8_s;

    xr[tid]       = X[(size_t)row * CH + tid];
    xr[tid + 256] = X[(size_t)row * CH + tid + 256];
    if (tid == 0) cnt = 0;

    float v[8];
#pragma unroll
    for (int i = 0; i < 8; i++) v[i] = -1e30f;
#pragma unroll
    for (int q = 0; q < 2; q++) {
        uint4 u = s4[tid + q * 256];
        uint32_t w[4] = {u.x, u.y, u.z, u.w};
#pragma unroll
        for (int t = 0; t < 4; t++) {
            __nv_bfloat162 p = *(__nv_bfloat162*)&w[t];
            ins8(v, __bfloat162float(p.x));
            ins8(v, __bfloat162float(p.y));
        }
    }
#pragma unroll
    for (int i = 0; i < 8; i++) sv[tid][i] = v[i];
    __syncthreads();
    for (int st = 128; st > 0; st >>= 1) {
        if (tid < st) {
#pragma unroll
            for (int i = 0; i < 8; i++) ins8(v, sv[tid + st][i]);
#pragma unroll
            for (int i = 0; i < 8; i++) sv[tid][i] = v[i];
        }
        __syncthreads();
    }
    if (tid == 0) thr8_s = sv[0][7];
    __syncthreads();
    const float thr8 = thr8_s;

#pragma unroll
    for (int q = 0; q < 2; q++) {
        int jv = tid + q * 256;
        uint4 u = s4[jv];
        uint32_t w[4] = {u.x, u.y, u.z, u.w};
#pragma unroll
        for (int t = 0; t < 4; t++) {
            __nv_bfloat162 p = *(__nv_bfloat162*)&w[t];
            if (__bfloat162float(p.x) >= thr8) {
                int pi = atomicAdd(&cnt, 1);
                if (pi < 32) cand[pi] = jv * 8 + t * 2;
            }
            if (__bfloat162float(p.y) >= thr8) {
                int pi = atomicAdd(&cnt, 1);
                if (pi < 32) cand[pi] = jv * 8 + t * 2 + 1;
            }
        }
    }
    __syncthreads();
    const int cn = min(cnt, 32);

    for (int c = warp; c < cn; c += 8) {
        const float* __restrict__ xc = X + (size_t)cand[c] * CH;
        float sum = 0.f;
        for (int k = lane; k < CH; k += 32) sum = fmaf(xr[k], xc[k], sum);
#pragma unroll
        for (int o = 16; o > 0; o >>= 1) sum += __shfl_xor_sync(0xffffffffu, sum, o);
        if (lane == 0) ex[c] = sum;
    }
    __syncthreads();

    if (tid == 0) {
        float tmp[32];
        for (int c = 0; c < cn; c++) tmp[c] = ex[c];
        float thr = -1e30f;
        for (int p = 0; p < 4; p++) {
            int bidx = 0; float bv = -1e30f;
            for (int c = 0; c < cn; c++) if (tmp[c] > bv) { bv = tmp[c]; bidx = c; }
            thr = bv; tmp[bidx] = -1e30f;
        }
        int d = 0;
        for (int c = 0; c < cn; c++) {
            if (ex[c] >= thr) { if (d < 16) g_idx[row * 16 + d] = cand[c]; d++; }
        }
        g_deg[row]  = min(d, 16);
        g_dinv[row] = rsqrtf((float)d);
    }
}

// ======== split-bf16 linear, 128x128, ldmatrix + cp.async 2-stage pipeline ========
// smem stage layout (bytes): Ah +0, Al +6144, Bh +12288, Bl +18432; stage stride 24576.
// mode 0: A = xh/xl; z=0 -> U -> g_u, z=1 -> V -> g_v.   mode 2: A = hh/hl -> Cout.
__global__ __launch_bounds__(256, 2) void lin_mma(const float* __restrict__ ba,
                                                  const float* __restrict__ bb,
                                                  float* __restrict__ Cout,
                                                  int ncols, int mode)
{
    const bool z1 = (mode == 0) && (blockIdx.z == 1);
    const __nv_bfloat16* __restrict__ Ahs = (mode == 2) ? g_hh : g_xh;
    const __nv_bfloat16* __restrict__ Als = (mode == 2) ? g_hl : g_xl;
    const __nv_bfloat16* __restrict__ Wh  = (mode == 2) ? g_fwh : (z1 ? g_vwh : g_uwh);
    const __nv_bfloat16* __restrict__ Wl  = (mode == 2) ? g_fwl : (z1 ? g_vwl : g_uwl);
    const float* __restrict__ bias = z1 ? bb : ba;
    float* __restrict__ Co = (mode == 0) ? (z1 ? g_v : g_u) : Cout;

    const int n0 = blockIdx.x * 128, m0 = blockIdx.y * 128;

    __shared__ __align__(16) __nv_bfloat16 sbuf[2][4][128 * SK];  // 49152 B
    const uint32_t S_u = (uint32_t)__cvta_generic_to_shared(sbuf);

    const int tid  = threadIdx.x;
    const int warp = tid >> 5, lane = tid & 31;
    const int wm = warp & 3, wn = warp >> 2;
    const int grp = lane >> 2, qd = lane & 3;
    const int l7 = lane & 7;

    const uint32_t a_off = ((wm * 32 + ((lane >> 3) & 1) * 8 + l7) * SK + ((lane >> 4) & 1) * 8) * 2;
    const uint32_t b_off = ((wn * 64 + ((lane >> 4) & 1) * 8 + l7) * SK + ((lane >> 3) & 1) * 8) * 2;

    float acc[2][8][4];
#pragma unroll
    for (int mi = 0; mi < 2; mi++)
#pragma unroll
        for (int ni = 0; ni < 8; ni++)
#pragma unroll
            for (int e = 0; e < 4; e++) acc[mi][ni][e] = 0.f;

    const int rr = tid >> 1;
    const int sg = (tid & 1) * 8;
    const uint32_t soff = (uint32_t)(rr * SK + sg) * 2;
    const size_t ga = (size_t)(m0 + rr) * CH + sg;
    const size_t gb = (size_t)(n0 + rr) * CH + sg;

    {
        uint32_t b = S_u + soff;
        cpa16(b,         Ahs + ga);
        cpa16(b + 6144,  Als + ga);
        cpa16(b + 12288, Wh + gb);
        cpa16(b + 18432, Wl + gb);
        cpa_commit();
    }

    for (int k = 0; k < NKIT; k++) {
        const int cur = k & 1;
        if (k + 1 < NKIT) {
            uint32_t b = S_u + (cur ^ 1) * 24576 + soff;
            int k0 = (k + 1) * 16;
            cpa16(b,         Ahs + ga + k0);
            cpa16(b + 6144,  Als + ga + k0);
            cpa16(b + 12288, Wh + gb + k0);
            cpa16(b + 18432, Wl + gb + k0);
            cpa_commit();
            cpa_wait1();
        } else {
            cpa_wait0();
        }
        __syncthreads();

        const uint32_t base = S_u + cur * 24576;
        uint32_t ah[2][4], al[2][4];
        ldsm_x4(ah[0], base + a_off);
        ldsm_x4(ah[1], base + a_off + 16 * SK * 2);
        ldsm_x4(al[0], base + 6144 + a_off);
        ldsm_x4(al[1], base + 6144 + a_off + 16 * SK * 2);
#pragma unroll
        for (int ni = 0; ni < 8; ni += 2) {
            uint32_t bh4[4], bl4[4];
            ldsm_x4(bh4, base + 12288 + b_off + ni * 8 * SK * 2);
            ldsm_x4(bl4, base + 18432 + b_off + ni * 8 * SK * 2);
#pragma unroll
            for (int mi = 0; mi < 2; mi++) {
                mma16816(acc[mi][ni],     ah[mi], &bh4[0]);
                mma16816(acc[mi][ni + 1], ah[mi], &bh4[2]);
                mma16816(acc[mi][ni],     ah[mi], &bl4[0]);
                mma16816(acc[mi][ni + 1], ah[mi], &bl4[2]);
                mma16816(acc[mi][ni],     al[mi], &bh4[0]);
                mma16816(acc[mi][ni + 1], al[mi], &bh4[2]);
            }
        }
        __syncthreads();
    }

#pragma unroll
    for (int mi = 0; mi < 2; mi++) {
        int m = m0 + wm * 32 + mi * 16 + grp;
#pragma unroll
        for (int ni = 0; ni < 8; ni++) {
            int n = n0 + wn * 64 + ni * 8 + qd * 2;
            float b0 = bias[n], b1 = bias[n + 1];
            *(float2*)(Co + (size_t)m * ncols + n) =
                make_float2(acc[mi][ni][0] + b0, acc[mi][ni][1] + b1);
            *(float2*)(Co + (size_t)(m + 8) * ncols + n) =
                make_float2(acc[mi][ni][2] + b0, acc[mi][ni][3] + b1);
        }
    }
}

// ====== K4: sparse aggregate + per-row norm + relu; writes hi/lo bf16 h ======
__global__ __launch_bounds__(128) void combine_kernel(const float* __restrict__ X)
{
    const int row = blockIdx.x, tid = threadIdx.x;
    const int warp = tid >> 5, lane = tid & 31;
    __shared__ int   nidx[16];
    __shared__ float nw[16];
    __shared__ float wred[4];
    __shared__ float mean_s, inv_s;

    const int   deg = g_deg[row];
    const float di  = g_dinv[row];
    if (tid < deg) {
        int j = g_idx[row * 16 + tid];
        nidx[tid] = j;
        nw[tid]   = di * g_dinv[j];
    }
    __syncthreads();

    const int c = tid * 4;
    float4 a = *(const float4*)&g_u[(size_t)row * CH + c];
    for (int t = 0; t < deg; t++) {
        float4 vv = *(const float4*)&g_v[(size_t)nidx[t] * CH + c];
        float w = nw[t];
        a.x = fmaf(w, vv.x, a.x); a.y = fmaf(w, vv.y, a.y);
        a.z = fmaf(w, vv.z, a.z); a.w = fmaf(w, vv.w, a.w);
    }

    float s = a.x + a.y + a.z + a.w;
#pragma unroll
    for (int o = 16; o > 0; o >>= 1) s += __shfl_xor_sync(0xffffffffu, s, o);
    if (lane == 0) wred[warp] = s;
    __syncthreads();
    if (tid == 0) mean_s = (wred[0] + wred[1] + wred[2] + wred[3]) * (1.f / CH);
    __syncthreads();
    const float mean = mean_s;

    float d0 = a.x - mean, d1 = a.y - mean, d2 = a.z - mean, d3 = a.w - mean;
    float vs = d0 * d0 + d1 * d1 + d2 * d2 + d3 * d3;
#pragma unroll
    for (int o = 16; o > 0; o >>= 1) vs += __shfl_xor_sync(0xffffffffu, vs, o);
    if (lane == 0) wred[warp] = vs;
    __syncthreads();
    if (tid == 0) inv_s = rsqrtf((wred[0] + wred[1] + wred[2] + wred[3]) * (1.f / CH) + EPSV);
    __syncthreads();
    const float inv = inv_s;

    float4 xv = *(const float4*)&X[(size_t)row * CH + c];
    float h[4];
    h[0] = fmaxf(xv.x + d0 * inv, 0.f);
    h[1] = fmaxf(xv.y + d1 * inv, 0.f);
    h[2] = fmaxf(xv.z + d2 * inv, 0.f);
    h[3] = fmaxf(xv.w + d3 * inv, 0.f);

    uint32_t hw[2], lw[2];
#pragma unroll
    for (int p = 0; p < 2; p++) {
        __nv_bfloat16 b0 = __float2bfloat16_rn(h[p * 2]);
        __nv_bfloat16 b1 = __float2bfloat16_rn(h[p * 2 + 1]);
        __nv_bfloat162 hp; hp.x = b0; hp.y = b1;
        __nv_bfloat162 lp = __floats2bfloat162_rn(h[p * 2] - __bfloat162float(b0),
                                                  h[p * 2 + 1] - __bfloat162float(b1));
        hw[p] = *(uint32_t*)&hp;
        lw[p] = *(uint32_t*)&lp;
    }
    *(uint2*)&g_hh[(size_t)row * CH + c] = make_uint2(hw[0], hw[1]);
    *(uint2*)&g_hl[(size_t)row * CH + c] = make_uint2(lw[0], lw[1]);
}

// ================= launch =================
extern "C" void kernel_launch(void* const* d_in, const int* in_sizes, int n_in,
                              void* d_out, int out_size)
{
    const float* x  = (const float*)d_in[0];
    const float* Uw = (const float*)d_in[1];
    const float* Ub = (const float*)d_in[2];
    const float* Vw = (const float*)d_in[3];
    const float* Vb = (const float*)d_in[4];
    const float* Fw = (const float*)d_in[5];
    const float* Fb = (const float*)d_in[6];
    float* out = (float*)d_out;

    split_kernel<<<2688, 256>>>(x, Uw, Vw, Fw);
    si_mma<<<dim3(32, 32), 256>>>();
    topk_refine<<<NPTS, 256>>>(x);
    lin_mma<<<dim3(4, 32, 2), 256>>>(Ub, Vb, nullptr, CH, 0);    // fused u,v
    combine_kernel<<<NPTS, 128>>>(x);
    lin_mma<<<dim3(2, 32, 1), 256>>>(Fb, nullptr, out, OUTF, 2); // fc
}

// round 11
// speedup vs baseline: 1.0462x; 1.0462x over previous
#include <cuda_runtime.h>
#include <cuda_bf16.h>
#include <cstdint>

#define NPTS 4096
#define CH   512
#define OUTF 256
#define EPSV 1e-5f
#define SA   40   // smem k-stride (bf16): 80B rows -> conflict-free ldmatrix

// ---------------- scratch (device-side only) ----------------
__device__ __nv_bfloat16 g_sib[(size_t)NPTS * NPTS];
__device__ float g_u [(size_t)NPTS * CH];
__device__ float g_v [(size_t)NPTS * CH];
__device__ float g_dinv[NPTS];
__device__ int   g_deg [NPTS];
__device__ int   g_idx [NPTS * 16];
__device__ __nv_bfloat16 g_xh[(size_t)NPTS * CH], g_xl[(size_t)NPTS * CH];
__device__ __nv_bfloat16 g_uwh[CH * CH],  g_uwl[CH * CH];
__device__ __nv_bfloat16 g_vwh[CH * CH],  g_vwl[CH * CH];
__device__ __nv_bfloat16 g_fwh[OUTF * CH], g_fwl[OUTF * CH];
__device__ __nv_bfloat16 g_hh[(size_t)NPTS * CH], g_hl[(size_t)NPTS * CH];

__device__ __forceinline__ void mma16816(float c[4], const uint32_t a[4], const uint32_t b[2])
{
    asm volatile(
        "mma.sync.aligned.m16n8k16.row.col.f32.bf16.bf16.f32 "
        "{%0,%1,%2,%3}, {%4,%5,%6,%7}, {%8,%9}, {%0,%1,%2,%3};"
        : "+f"(c[0]), "+f"(c[1]), "+f"(c[2]), "+f"(c[3])
        : "r"(a[0]), "r"(a[1]), "r"(a[2]), "r"(a[3]), "r"(b[0]), "r"(b[1]));
}

__device__ __forceinline__ void ldsm_x4(uint32_t r[4], uint32_t saddr)
{
    asm volatile("ldmatrix.sync.aligned.m8n8.x4.shared.b16 {%0,%1,%2,%3}, [%4];"
                 : "=r"(r[0]), "=r"(r[1]), "=r"(r[2]), "=r"(r[3]) : "r"(saddr));
}

// ================= K0: one-shot hi/lo bf16 split of x, Uw, Vw, fc_w =================
__global__ __launch_bounds__(256) void split_kernel(const float* __restrict__ X,
                                                    const float* __restrict__ Uw,
                                                    const float* __restrict__ Vw,
                                                    const float* __restrict__ Fw)
{
    size_t i = (size_t)blockIdx.x * 256 + threadIdx.x;
    const float* src; __nv_bfloat16 *dh, *dl; size_t off;
    if (i < 524288)      { src = X;  dh = g_xh;  dl = g_xl;  off = i; }
    else if (i < 589824) { src = Uw; dh = g_uwh; dl = g_uwl; off = i - 524288; }
    else if (i < 655360) { src = Vw; dh = g_vwh; dl = g_vwl; off = i - 589824; }
    else                 { src = Fw; dh = g_fwh; dl = g_fwl; off = i - 655360; }

    float4 v = ((const float4*)src)[off];
    float f[4] = {v.x, v.y, v.z, v.w};
    uint32_t hw[2], lw[2];
#pragma unroll
    for (int p = 0; p < 2; p++) {
        __nv_bfloat16 h0 = __float2bfloat16_rn(f[p * 2]);
        __nv_bfloat16 h1 = __float2bfloat16_rn(f[p * 2 + 1]);
        __nv_bfloat162 hp; hp.x = h0; hp.y = h1;
        __nv_bfloat162 lp = __floats2bfloat162_rn(f[p * 2] - __bfloat162float(h0),
                                                  f[p * 2 + 1] - __bfloat162float(h1));
        hw[p] = *(uint32_t*)&hp;
        lw[p] = *(uint32_t*)&lp;
    }
    *(uint2*)&dh[off * 4] = make_uint2(hw[0], hw[1]);
    *(uint2*)&dl[off * 4] = make_uint2(lw[0], lw[1]);
}

// ===== K1: si = xh@xh.T, upper-tri blocks + smem-transposed mirror; ldmatrix =====
__global__ __launch_bounds__(256, 2) void si_mma()
{
    const int bj = blockIdx.x, bi = blockIdx.y;
    if (bi > bj) return;
    const int m0 = bi * 128, n0 = bj * 128;

    __shared__ __align__(16) unsigned char sraw[128 * 136 * 2];
    __nv_bfloat16* As = reinterpret_cast<__nv_bfloat16*>(sraw);
    __nv_bfloat16* Bs = As + 128 * SA;
    __nv_bfloat16* Ts = reinterpret_cast<__nv_bfloat16*>(sraw);

    const int tid  = threadIdx.x;
    const int warp = tid >> 5, lane = tid & 31;
    const int wm = warp & 3, wn = warp >> 2;
    const int grp = lane >> 2, qd = lane & 3;
    const int l7 = lane & 7;

    const uint32_t As_u = (uint32_t)__cvta_generic_to_shared(As);
    const uint32_t Bs_u = (uint32_t)__cvta_generic_to_shared(Bs);
    const uint32_t a_off = ((wm * 32 + ((lane >> 3) & 1) * 8 + l7) * SA + ((lane >> 4) & 1) * 8) * 2;
    const uint32_t b_off = ((wn * 64 + ((lane >> 4) & 1) * 8 + l7) * SA + ((lane >> 3) & 1) * 8) * 2;

    float acc[2][8][4];
#pragma unroll
    for (int mi = 0; mi < 2; mi++)
#pragma unroll
        for (int ni = 0; ni < 8; ni++)
#pragma unroll
            for (int e = 0; e < 4; e++) acc[mi][ni][e] = 0.f;

    const int ldr = tid >> 2;
    const int seg = (tid & 3) * 8;

    for (int k0 = 0; k0 < CH; k0 += 32) {
#pragma unroll
        for (int p = 0; p < 2; p++) {
            int rr = ldr + p * 64;
            *(uint4*)&As[rr * SA + seg] = *(const uint4*)&g_xh[(size_t)(m0 + rr) * CH + k0 + seg];
            *(uint4*)&Bs[rr * SA + seg] = *(const uint4*)&g_xh[(size_t)(n0 + rr) * CH + k0 + seg];
        }
        __syncthreads();
#pragma unroll
        for (int kk = 0; kk < 32; kk += 16) {
            uint32_t afr[2][4];
#pragma unroll
            for (int mi = 0; mi < 2; mi++)
                ldsm_x4(afr[mi], As_u + a_off + (mi * 16 * SA + kk) * 2);
#pragma unroll
            for (int ni = 0; ni < 8; ni += 2) {
                uint32_t b4[4];
                ldsm_x4(b4, Bs_u + b_off + (ni * 8 * SA + kk) * 2);
#pragma unroll
                for (int mi = 0; mi < 2; mi++) {
                    mma16816(acc[mi][ni],     afr[mi], &b4[0]);
                    mma16816(acc[mi][ni + 1], afr[mi], &b4[2]);
                }
            }
        }
        __syncthreads();
    }

#pragma unroll
    for (int mi = 0; mi < 2; mi++) {
        int m = m0 + wm * 32 + mi * 16 + grp;
#pragma unroll
        for (int ni = 0; ni < 8; ni++) {
            int n = n0 + wn * 64 + ni * 8 + qd * 2;
            *(__nv_bfloat162*)&g_sib[(size_t)m * NPTS + n] =
                __floats2bfloat162_rn(acc[mi][ni][0], acc[mi][ni][1]);
            *(__nv_bfloat162*)&g_sib[(size_t)(m + 8) * NPTS + n] =
                __floats2bfloat162_rn(acc[mi][ni][2], acc[mi][ni][3]);
        }
    }

    if (bi != bj) {
#pragma unroll
        for (int mi = 0; mi < 2; mi++) {
            int ml = wm * 32 + mi * 16 + grp;
#pragma unroll
            for (int ni = 0; ni < 8; ni++) {
                int nl = wn * 64 + ni * 8 + qd * 2;
                Ts[nl * 136 + ml]           = __float2bfloat16_rn(acc[mi][ni][0]);
                Ts[(nl + 1) * 136 + ml]     = __float2bfloat16_rn(acc[mi][ni][1]);
                Ts[nl * 136 + ml + 8]       = __float2bfloat16_rn(acc[mi][ni][2]);
                Ts[(nl + 1) * 136 + ml + 8] = __float2bfloat16_rn(acc[mi][ni][3]);
            }
        }
        __syncthreads();
        const int r = tid >> 1, hh = (tid & 1) * 64;
#pragma unroll
        for (int i = 0; i < 8; i++) {
            *(uint4*)&g_sib[(size_t)(n0 + r) * NPTS + m0 + hh + i * 8] =
                *(const uint4*)&Ts[r * 136 + hh + i * 8];
        }
    }
}

// ================= K2: approx top-8 candidates + fp32 exact refine =================
__device__ __forceinline__ void ins8(float v[8], float x)
{
    if (x > v[7]) {
        v[7] = x;
#pragma unroll
        for (int i = 7; i > 0; i--) {
            if (v[i] > v[i - 1]) { float t = v[i]; v[i] = v[i - 1]; v[i - 1] = t; }
        }
    }
}

__global__ __launch_bounds__(256) void topk_refine(const float* __restrict__ X)
{
    const int row = blockIdx.x;
    const int tid = threadIdx.x;
    const int warp = tid >> 5, lane = tid & 31;
    const uint4* __restrict__ s4 = (const uint4*)(g_sib + (size_t)row * NPTS);

    __shared__ float sv[256][8];
    __shared__ float xr[CH];
    __shared__ float ex[32];
    __shared__ int   cand[32];
    __shared__ int   cnt;
    __shared__ float thr8_s;

    xr[tid]       = X[(size_t)row * CH + tid];
    xr[tid + 256] = X[(size_t)row * CH + tid + 256];
    if (tid == 0) cnt = 0;

    float v[8];
#pragma unroll
    for (int i = 0; i < 8; i++) v[i] = -1e30f;
#pragma unroll
    for (int q = 0; q < 2; q++) {
        uint4 u = s4[tid + q * 256];
        uint32_t w[4] = {u.x, u.y, u.z, u.w};
#pragma unroll
        for (int t = 0; t < 4; t++) {
            __nv_bfloat162 p = *(__nv_bfloat162*)&w[t];
            ins8(v, __bfloat162float(p.x));
            ins8(v, __bfloat162float(p.y));
        }
    }
#pragma unroll
    for (int i = 0; i < 8; i++) sv[tid][i] = v[i];
    __syncthreads();
    for (int st = 128; st > 0; st >>= 1) {
        if (tid < st) {
#pragma unroll
            for (int i = 0; i < 8; i++) ins8(v, sv[tid + st][i]);
#pragma unroll
            for (int i = 0; i < 8; i++) sv[tid][i] = v[i];
        }
        __syncthreads();
    }
    if (tid == 0) thr8_s = sv[0][7];
    __syncthreads();
    const float thr8 = thr8_s;

#pragma unroll
    for (int q = 0; q < 2; q++) {
        int jv = tid + q * 256;
        uint4 u = s4[jv];
        uint32_t w[4] = {u.x, u.y, u.z, u.w};
#pragma unroll
        for (int t = 0; t < 4; t++) {
            __nv_bfloat162 p = *(__nv_bfloat162*)&w[t];
            if (__bfloat162float(p.x) >= thr8) {
                int pi = atomicAdd(&cnt, 1);
                if (pi < 32) cand[pi] = jv * 8 + t * 2;
            }
            if (__bfloat162float(p.y) >= thr8) {
                int pi = atomicAdd(&cnt, 1);
                if (pi < 32) cand[pi] = jv * 8 + t * 2 + 1;
            }
        }
    }
    __syncthreads();
    const int cn = min(cnt, 32);

    for (int c = warp; c < cn; c += 8) {
        const float* __restrict__ xc = X + (size_t)cand[c] * CH;
        float sum = 0.f;
        for (int k = lane; k < CH; k += 32) sum = fmaf(xr[k], xc[k], sum);
#pragma unroll
        for (int o = 16; o > 0; o >>= 1) sum += __shfl_xor_sync(0xffffffffu, sum, o);
        if (lane == 0) ex[c] = sum;
    }
    __syncthreads();

    if (tid == 0) {
        float tmp[32];
        for (int c = 0; c < cn; c++) tmp[c] = ex[c];
        float thr = -1e30f;
        for (int p = 0; p < 4; p++) {
            int bidx = 0; float bv = -1e30f;
            for (int c = 0; c < cn; c++) if (tmp[c] > bv) { bv = tmp[c]; bidx = c; }
            thr = bv; tmp[bidx] = -1e30f;
        }
        int d = 0;
        for (int c = 0; c < cn; c++) {
            if (ex[c] >= thr) { if (d < 16) g_idx[row * 16 + d] = cand[c]; d++; }
        }
        g_deg[row]  = min(d, 16);
        g_dinv[row] = rsqrtf((float)d);
    }
}

// ======== split-bf16 linear, 128x128, ldmatrix; product-major MMA ordering ========
// Inner loop holds B hi/lo fragments for an ni-group of 4 and issues the 24 MMAs
// product-major (hh x8, hl x8, lh x8) -> same-accumulator reuse distance 8.
// mode 0: A = xh/xl; z=0 -> U -> g_u, z=1 -> V -> g_v.   mode 2: A = hh/hl -> Cout.
__global__ __launch_bounds__(256, 2) void lin_mma(const float* __restrict__ ba,
                                                  const float* __restrict__ bb,
                                                  float* __restrict__ Cout,
                                                  int ncols, int mode)
{
    const bool z1 = (mode == 0) && (blockIdx.z == 1);
    const __nv_bfloat16* __restrict__ Ahs = (mode == 2) ? g_hh : g_xh;
    const __nv_bfloat16* __restrict__ Als = (mode == 2) ? g_hl : g_xl;
    const __nv_bfloat16* __restrict__ Wh  = (mode == 2) ? g_fwh : (z1 ? g_vwh : g_uwh);
    const __nv_bfloat16* __restrict__ Wl  = (mode == 2) ? g_fwl : (z1 ? g_vwl : g_uwl);
    const float* __restrict__ bias = z1 ? bb : ba;
    float* __restrict__ Co = (mode == 0) ? (z1 ? g_v : g_u) : Cout;

    const int n0 = blockIdx.x * 128, m0 = blockIdx.y * 128;

    __shared__ __nv_bfloat16 Ah[128 * SA], Al[128 * SA];
    __shared__ __nv_bfloat16 Bh[128 * SA], Bl[128 * SA];

    const int tid  = threadIdx.x;
    const int warp = tid >> 5, lane = tid & 31;
    const int wm = warp & 3, wn = warp >> 2;
    const int grp = lane >> 2, qd = lane & 3;
    const int l7 = lane & 7;

    const uint32_t Ah_u = (uint32_t)__cvta_generic_to_shared(Ah);
    const uint32_t Al_u = (uint32_t)__cvta_generic_to_shared(Al);
    const uint32_t Bh_u = (uint32_t)__cvta_generic_to_shared(Bh);
    const uint32_t Bl_u = (uint32_t)__cvta_generic_to_shared(Bl);
    const uint32_t a_off = ((wm * 32 + ((lane >> 3) & 1) * 8 + l7) * SA + ((lane >> 4) & 1) * 8) * 2;
    const uint32_t b_off = ((wn * 64 + ((lane >> 4) & 1) * 8 + l7) * SA + ((lane >> 3) & 1) * 8) * 2;

    float acc[2][8][4];
#pragma unroll
    for (int mi = 0; mi < 2; mi++)
#pragma unroll
        for (int ni = 0; ni < 8; ni++)
#pragma unroll
            for (int e = 0; e < 4; e++) acc[mi][ni][e] = 0.f;

    const int ldr = tid >> 2;
    const int seg = (tid & 3) * 8;

    for (int k0 = 0; k0 < CH; k0 += 32) {
#pragma unroll
        for (int p = 0; p < 2; p++) {
            int rr = ldr + p * 64;
            *(uint4*)&Ah[rr * SA + seg] = *(const uint4*)&Ahs[(size_t)(m0 + rr) * CH + k0 + seg];
            *(uint4*)&Al[rr * SA + seg] = *(const uint4*)&Als[(size_t)(m0 + rr) * CH + k0 + seg];
            *(uint4*)&Bh[rr * SA + seg] = *(const uint4*)&Wh[(size_t)(n0 + rr) * CH + k0 + seg];
            *(uint4*)&Bl[rr * SA + seg] = *(const uint4*)&Wl[(size_t)(n0 + rr) * CH + k0 + seg];
        }
        __syncthreads();
#pragma unroll
        for (int kk = 0; kk < 32; kk += 16) {
            uint32_t ah[2][4], al[2][4];
#pragma unroll
            for (int mi = 0; mi < 2; mi++) {
                ldsm_x4(ah[mi], Ah_u + a_off + (mi * 16 * SA + kk) * 2);
                ldsm_x4(al[mi], Al_u + a_off + (mi * 16 * SA + kk) * 2);
            }
#pragma unroll
            for (int nb = 0; nb < 8; nb += 4) {
                // B fragments for pairs (nb, nb+2): hi and lo — 16 regs live
                uint32_t bh4[2][4], bl4[2][4];
                ldsm_x4(bh4[0], Bh_u + b_off + (nb * 8 * SA + kk) * 2);
                ldsm_x4(bh4[1], Bh_u + b_off + ((nb + 2) * 8 * SA + kk) * 2);
                ldsm_x4(bl4[0], Bl_u + b_off + (nb * 8 * SA + kk) * 2);
                ldsm_x4(bl4[1], Bl_u + b_off + ((nb + 2) * 8 * SA + kk) * 2);
                // product-major: hh (8 MMAs), then hl (8), then lh (8)
#pragma unroll
                for (int q = 0; q < 2; q++)
#pragma unroll
                    for (int mi = 0; mi < 2; mi++) {
                        mma16816(acc[mi][nb + 2 * q],     ah[mi], &bh4[q][0]);
                        mma16816(acc[mi][nb + 2 * q + 1], ah[mi], &bh4[q][2]);
                    }
#pragma unroll
                for (int q = 0; q < 2; q++)
#pragma unroll
                    for (int mi = 0; mi < 2; mi++) {
                        mma16816(acc[mi][nb + 2 * q],     ah[mi], &bl4[q][0]);
                        mma16816(acc[mi][nb + 2 * q + 1], ah[mi], &bl4[q][2]);
                    }
#pragma unroll
                for (int q = 0; q < 2; q++)
#pragma unroll
                    for (int mi = 0; mi < 2; mi++) {
                        mma16816(acc[mi][nb + 2 * q],     al[mi], &bh4[q][0]);
                        mma16816(acc[mi][nb + 2 * q + 1], al[mi], &bh4[q][2]);
                    }
            }
        }
        __syncthreads();
    }

#pragma unroll
    for (int mi = 0; mi < 2; mi++) {
        int m = m0 + wm * 32 + mi * 16 + grp;
#pragma unroll
        for (int ni = 0; ni < 8; ni++) {
            int n = n0 + wn * 64 + ni * 8 + qd * 2;
            float b0 = bias[n], b1 = bias[n + 1];
            *(float2*)(Co + (size_t)m * ncols + n) =
                make_float2(acc[mi][ni][0] + b0, acc[mi][ni][1] + b1);
            *(float2*)(Co + (size_t)(m + 8) * ncols + n) =
                make_float2(acc[mi][ni][2] + b0, acc[mi][ni][3] + b1);
        }
    }
}

// ====== K4: sparse aggregate + per-row norm + relu; writes hi/lo bf16 h ======
__global__ __launch_bounds__(128) void combine_kernel(const float* __restrict__ X)
{
    const int row = blockIdx.x, tid = threadIdx.x;
    const int warp = tid >> 5, lane = tid & 31;
    __shared__ int   nidx[16];
    __shared__ float nw[16];
    __shared__ float wred[4];
    __shared__ float mean_s, inv_s;

    const int   deg = g_deg[row];
    const float di  = g_dinv[row];
    if (tid < deg) {
        int j = g_idx[row * 16 + tid];
        nidx[tid] = j;
        nw[tid]   = di * g_dinv[j];
    }
    __syncthreads();

    const int c = tid * 4;
    float4 a = *(const float4*)&g_u[(size_t)row * CH + c];
    for (int t = 0; t < deg; t++) {
        float4 vv = *(const float4*)&g_v[(size_t)nidx[t] * CH + c];
        float w = nw[t];
        a.x = fmaf(w, vv.x, a.x); a.y = fmaf(w, vv.y, a.y);
        a.z = fmaf(w, vv.z, a.z); a.w = fmaf(w, vv.w, a.w);
    }

    float s = a.x + a.y + a.z + a.w;
#pragma unroll
    for (int o = 16; o > 0; o >>= 1) s += __shfl_xor_sync(0xffffffffu, s, o);
    if (lane == 0) wred[warp] = s;
    __syncthreads();
    if (tid == 0) mean_s = (wred[0] + wred[1] + wred[2] + wred[3]) * (1.f / CH);
    __syncthreads();
    const float mean = mean_s;

    float d0 = a.x - mean, d1 = a.y - mean, d2 = a.z - mean, d3 = a.w - mean;
    float vs = d0 * d0 + d1 * d1 + d2 * d2 + d3 * d3;
#pragma unroll
    for (int o = 16; o > 0; o >>= 1) vs += __shfl_xor_sync(0xffffffffu, vs, o);
    if (lane == 0) wred[warp] = vs;
    __syncthreads();
    if (tid == 0) inv_s = rsqrtf((wred[0] + wred[1] + wred[2] + wred[3]) * (1.f / CH) + EPSV);
    __syncthreads();
    const float inv = inv_s;

    float4 xv = *(const float4*)&X[(size_t)row * CH + c];
    float h[4];
    h[0] = fmaxf(xv.x + d0 * inv, 0.f);
    h[1] = fmaxf(xv.y + d1 * inv, 0.f);
    h[2] = fmaxf(xv.z + d2 * inv, 0.f);
    h[3] = fmaxf(xv.w + d3 * inv, 0.f);

    uint32_t hw[2], lw[2];
#pragma unroll
    for (int p = 0; p < 2; p++) {
        __nv_bfloat16 b0 = __float2bfloat16_rn(h[p * 2]);
        __nv_bfloat16 b1 = __float2bfloat16_rn(h[p * 2 + 1]);
        __nv_bfloat162 hp; hp.x = b0; hp.y = b1;
        __nv_bfloat162 lp = __floats2bfloat162_rn(h[p * 2] - __bfloat162float(b0),
                                                  h[p * 2 + 1] - __bfloat162float(b1));
        hw[p] = *(uint32_t*)&hp;
        lw[p] = *(uint32_t*)&lp;
    }
    *(uint2*)&g_hh[(size_t)row * CH + c] = make_uint2(hw[0], hw[1]);
    *(uint2*)&g_hl[(size_t)row * CH + c] = make_uint2(lw[0], lw[1]);
}

// ================= launch =================
extern "C" void kernel_launch(void* const* d_in, const int* in_sizes, int n_in,
                              void* d_out, int out_size)
{
    const float* x  = (const float*)d_in[0];
    const float* Uw = (const float*)d_in[1];
    const float* Ub = (const float*)d_in[2];
    const float* Vw = (const float*)d_in[3];
    const float* Vb = (const float*)d_in[4];
    const float* Fw = (const float*)d_in[5];
    const float* Fb = (const float*)d_in[6];
    float* out = (float*)d_out;

    split_kernel<<<2688, 256>>>(x, Uw, Vw, Fw);
    si_mma<<<dim3(32, 32), 256>>>();
    topk_refine<<<NPTS, 256>>>(x);
    lin_mma<<<dim3(4, 32, 2), 256>>>(Ub, Vb, nullptr, CH, 0);    // fused u,v
    combine_kernel<<<NPTS, 128>>>(x);
    lin_mma<<<dim3(2, 32, 1), 256>>>(Fb, nullptr, out, OUTF, 2); // fc
}

// round 12
// speedup vs baseline: 1.0820x; 1.0342x over previous
#include <cuda_runtime.h>
#include <cuda_bf16.h>
#include <cstdint>

#define NPTS 4096
#define CH   512
#define OUTF 256
#define EPSV 1e-5f
#define SA   40   // smem k-stride (bf16): 80B rows -> conflict-free ldmatrix

// ---------------- scratch (device-side only) ----------------
__device__ __nv_bfloat16 g_sib[(size_t)NPTS * NPTS];
__device__ float g_u [(size_t)NPTS * CH];
__device__ float g_v [(size_t)NPTS * CH];
__device__ float g_dinv[NPTS];
__device__ int   g_deg [NPTS];
__device__ int   g_idx [NPTS * 16];
__device__ __nv_bfloat16 g_xh[(size_t)NPTS * CH], g_xl[(size_t)NPTS * CH];
__device__ __nv_bfloat16 g_uwh[CH * CH],  g_uwl[CH * CH];
__device__ __nv_bfloat16 g_vwh[CH * CH],  g_vwl[CH * CH];
__device__ __nv_bfloat16 g_fwh[OUTF * CH], g_fwl[OUTF * CH];
__device__ __nv_bfloat16 g_hh[(size_t)NPTS * CH], g_hl[(size_t)NPTS * CH];

__device__ __forceinline__ void mma16816(float c[4], const uint32_t a[4], const uint32_t b[2])
{
    asm volatile(
        "mma.sync.aligned.m16n8k16.row.col.f32.bf16.bf16.f32 "
        "{%0,%1,%2,%3}, {%4,%5,%6,%7}, {%8,%9}, {%0,%1,%2,%3};"
        : "+f"(c[0]), "+f"(c[1]), "+f"(c[2]), "+f"(c[3])
        : "r"(a[0]), "r"(a[1]), "r"(a[2]), "r"(a[3]), "r"(b[0]), "r"(b[1]));
}

__device__ __forceinline__ void ldsm_x4(uint32_t r[4], uint32_t saddr)
{
    asm volatile("ldmatrix.sync.aligned.m8n8.x4.shared.b16 {%0,%1,%2,%3}, [%4];"
                 : "=r"(r[0]), "=r"(r[1]), "=r"(r[2]), "=r"(r[3]) : "r"(saddr));
}

// ================= K0: one-shot hi/lo bf16 split of x, Uw, Vw, fc_w =================
__global__ __launch_bounds__(256) void split_kernel(const float* __restrict__ X,
                                                    const float* __restrict__ Uw,
                                                    const float* __restrict__ Vw,
                                                    const float* __restrict__ Fw)
{
    size_t i = (size_t)blockIdx.x * 256 + threadIdx.x;
    const float* src; __nv_bfloat16 *dh, *dl; size_t off;
    if (i < 524288)      { src = X;  dh = g_xh;  dl = g_xl;  off = i; }
    else if (i < 589824) { src = Uw; dh = g_uwh; dl = g_uwl; off = i - 524288; }
    else if (i < 655360) { src = Vw; dh = g_vwh; dl = g_vwl; off = i - 589824; }
    else                 { src = Fw; dh = g_fwh; dl = g_fwl; off = i - 655360; }

    float4 v = ((const float4*)src)[off];
    float f[4] = {v.x, v.y, v.z, v.w};
    uint32_t hw[2], lw[2];
#pragma unroll
    for (int p = 0; p < 2; p++) {
        __nv_bfloat16 h0 = __float2bfloat16_rn(f[p * 2]);
        __nv_bfloat16 h1 = __float2bfloat16_rn(f[p * 2 + 1]);
        __nv_bfloat162 hp; hp.x = h0; hp.y = h1;
        __nv_bfloat162 lp = __floats2bfloat162_rn(f[p * 2] - __bfloat162float(h0),
                                                  f[p * 2 + 1] - __bfloat162float(h1));
        hw[p] = *(uint32_t*)&hp;
        lw[p] = *(uint32_t*)&lp;
    }
    *(uint2*)&dh[off * 4] = make_uint2(hw[0], hw[1]);
    *(uint2*)&dl[off * 4] = make_uint2(lw[0], lw[1]);
}

// ===== K1: si = xh@xh.T, upper-tri blocks + smem-transposed mirror; ldmatrix =====
__global__ __launch_bounds__(256, 2) void si_mma()
{
    const int bj = blockIdx.x, bi = blockIdx.y;
    if (bi > bj) return;
    const int m0 = bi * 128, n0 = bj * 128;

    __shared__ __align__(16) unsigned char sraw[128 * 136 * 2];
    __nv_bfloat16* As = reinterpret_cast<__nv_bfloat16*>(sraw);
    __nv_bfloat16* Bs = As + 128 * SA;
    __nv_bfloat16* Ts = reinterpret_cast<__nv_bfloat16*>(sraw);

    const int tid  = threadIdx.x;
    const int warp = tid >> 5, lane = tid & 31;
    const int wm = warp & 3, wn = warp >> 2;
    const int grp = lane >> 2, qd = lane & 3;
    const int l7 = lane & 7;

    const uint32_t As_u = (uint32_t)__cvta_generic_to_shared(As);
    const uint32_t Bs_u = (uint32_t)__cvta_generic_to_shared(Bs);
    const uint32_t a_off = ((wm * 32 + ((lane >> 3) & 1) * 8 + l7) * SA + ((lane >> 4) & 1) * 8) * 2;
    const uint32_t b_off = ((wn * 64 + ((lane >> 4) & 1) * 8 + l7) * SA + ((lane >> 3) & 1) * 8) * 2;

    float acc[2][8][4];
#pragma unroll
    for (int mi = 0; mi < 2; mi++)
#pragma unroll
        for (int ni = 0; ni < 8; ni++)
#pragma unroll
            for (int e = 0; e < 4; e++) acc[mi][ni][e] = 0.f;

    const int ldr = tid >> 2;
    const int seg = (tid & 3) * 8;

    for (int k0 = 0; k0 < CH; k0 += 32) {
#pragma unroll
        for (int p = 0; p < 2; p++) {
            int rr = ldr + p * 64;
            *(uint4*)&As[rr * SA + seg] = *(const uint4*)&g_xh[(size_t)(m0 + rr) * CH + k0 + seg];
            *(uint4*)&Bs[rr * SA + seg] = *(const uint4*)&g_xh[(size_t)(n0 + rr) * CH + k0 + seg];
        }
        __syncthreads();
#pragma unroll
        for (int kk = 0; kk < 32; kk += 16) {
            uint32_t afr[2][4];
#pragma unroll
            for (int mi = 0; mi < 2; mi++)
                ldsm_x4(afr[mi], As_u + a_off + (mi * 16 * SA + kk) * 2);
#pragma unroll
            for (int ni = 0; ni < 8; ni += 2) {
                uint32_t b4[4];
                ldsm_x4(b4, Bs_u + b_off + (ni * 8 * SA + kk) * 2);
#pragma unroll
                for (int mi = 0; mi < 2; mi++) {
                    mma16816(acc[mi][ni],     afr[mi], &b4[0]);
                    mma16816(acc[mi][ni + 1], afr[mi], &b4[2]);
                }
            }
        }
        __syncthreads();
    }

#pragma unroll
    for (int mi = 0; mi < 2; mi++) {
        int m = m0 + wm * 32 + mi * 16 + grp;
#pragma unroll
        for (int ni = 0; ni < 8; ni++) {
            int n = n0 + wn * 64 + ni * 8 + qd * 2;
            *(__nv_bfloat162*)&g_sib[(size_t)m * NPTS + n] =
                __floats2bfloat162_rn(acc[mi][ni][0], acc[mi][ni][1]);
            *(__nv_bfloat162*)&g_sib[(size_t)(m + 8) * NPTS + n] =
                __floats2bfloat162_rn(acc[mi][ni][2], acc[mi][ni][3]);
        }
    }

    if (bi != bj) {
#pragma unroll
        for (int mi = 0; mi < 2; mi++) {
            int ml = wm * 32 + mi * 16 + grp;
#pragma unroll
            for (int ni = 0; ni < 8; ni++) {
                int nl = wn * 64 + ni * 8 + qd * 2;
                Ts[nl * 136 + ml]           = __float2bfloat16_rn(acc[mi][ni][0]);
                Ts[(nl + 1) * 136 + ml]     = __float2bfloat16_rn(acc[mi][ni][1]);
                Ts[nl * 136 + ml + 8]       = __float2bfloat16_rn(acc[mi][ni][2]);
                Ts[(nl + 1) * 136 + ml + 8] = __float2bfloat16_rn(acc[mi][ni][3]);
            }
        }
        __syncthreads();
        const int r = tid >> 1, hh = (tid & 1) * 64;
#pragma unroll
        for (int i = 0; i < 8; i++) {
            *(uint4*)&g_sib[(size_t)(n0 + r) * NPTS + m0 + hh + i * 8] =
                *(const uint4*)&Ts[r * 136 + hh + i * 8];
        }
    }
}

// ================= K2: approx top-8 candidates + fp32 exact refine =================
__device__ __forceinline__ void ins8(float v[8], float x)
{
    if (x > v[7]) {
        v[7] = x;
#pragma unroll
        for (int i = 7; i > 0; i--) {
            if (v[i] > v[i - 1]) { float t = v[i]; v[i] = v[i - 1]; v[i - 1] = t; }
        }
    }
}

__global__ __launch_bounds__(256) void topk_refine(const float* __restrict__ X)
{
    const int row = blockIdx.x;
    const int tid = threadIdx.x;
    const int warp = tid >> 5, lane = tid & 31;
    const uint4* __restrict__ s4 = (const uint4*)(g_sib + (size_t)row * NPTS);

    __shared__ float sv[256][8];
    __shared__ float xr[CH];
    __shared__ float ex[32];
    __shared__ int   cand[32];
    __shared__ int   cnt;
    __shared__ float thr8_s;

    xr[tid]       = X[(size_t)row * CH + tid];
    xr[tid + 256] = X[(size_t)row * CH + tid + 256];
    if (tid == 0) cnt = 0;

    float v[8];
#pragma unroll
    for (int i = 0; i < 8; i++) v[i] = -1e30f;
#pragma unroll
    for (int q = 0; q < 2; q++) {
        uint4 u = s4[tid + q * 256];
        uint32_t w[4] = {u.x, u.y, u.z, u.w};
#pragma unroll
        for (int t = 0; t < 4; t++) {
            __nv_bfloat162 p = *(__nv_bfloat162*)&w[t];
            ins8(v, __bfloat162float(p.x));
            ins8(v, __bfloat162float(p.y));
        }
    }
#pragma unroll
    for (int i = 0; i < 8; i++) sv[tid][i] = v[i];
    __syncthreads();
    for (int st = 128; st > 0; st >>= 1) {
        if (tid < st) {
#pragma unroll
            for (int i = 0; i < 8; i++) ins8(v, sv[tid + st][i]);
#pragma unroll
            for (int i = 0; i < 8; i++) sv[tid][i] = v[i];
        }
        __syncthreads();
    }
    if (tid == 0) thr8_s = sv[0][7];
    __syncthreads();
    const float thr8 = thr8_s;

#pragma unroll
    for (int q = 0; q < 2; q++) {
        int jv = tid + q * 256;
        uint4 u = s4[jv];
        uint32_t w[4] = {u.x, u.y, u.z, u.w};
#pragma unroll
        for (int t = 0; t < 4; t++) {
            __nv_bfloat162 p = *(__nv_bfloat162*)&w[t];
            if (__bfloat162float(p.x) >= thr8) {
                int pi = atomicAdd(&cnt, 1);
                if (pi < 32) cand[pi] = jv * 8 + t * 2;
            }
            if (__bfloat162float(p.y) >= thr8) {
                int pi = atomicAdd(&cnt, 1);
                if (pi < 32) cand[pi] = jv * 8 + t * 2 + 1;
            }
        }
    }
    __syncthreads();
    const int cn = min(cnt, 32);

    for (int c = warp; c < cn; c += 8) {
        const float* __restrict__ xc = X + (size_t)cand[c] * CH;
        float sum = 0.f;
        for (int k = lane; k < CH; k += 32) sum = fmaf(xr[k], xc[k], sum);
#pragma unroll
        for (int o = 16; o > 0; o >>= 1) sum += __shfl_xor_sync(0xffffffffu, sum, o);
        if (lane == 0) ex[c] = sum;
    }
    __syncthreads();

    if (tid == 0) {
        float tmp[32];
        for (int c = 0; c < cn; c++) tmp[c] = ex[c];
        float thr = -1e30f;
        for (int p = 0; p < 4; p++) {
            int bidx = 0; float bv = -1e30f;
            for (int c = 0; c < cn; c++) if (tmp[c] > bv) { bv = tmp[c]; bidx = c; }
            thr = bv; tmp[bidx] = -1e30f;
        }
        int d = 0;
        for (int c = 0; c < cn; c++) {
            if (ex[c] >= thr) { if (d < 16) g_idx[row * 16 + d] = cand[c]; d++; }
        }
        g_deg[row]  = min(d, 16);
        g_dinv[row] = rsqrtf((float)d);
    }
}

// ======== split-bf16 linear, 128x128, ldmatrix; product-major MMA ordering ========
__global__ __launch_bounds__(256, 2) void lin_mma(const float* __restrict__ ba,
                                                  const float* __restrict__ bb,
                                                  float* __restrict__ Cout,
                                                  int ncols, int mode)
{
    const bool z1 = (mode == 0) && (blockIdx.z == 1);
    const __nv_bfloat16* __restrict__ Ahs = (mode == 2) ? g_hh : g_xh;
    const __nv_bfloat16* __restrict__ Als = (mode == 2) ? g_hl : g_xl;
    const __nv_bfloat16* __restrict__ Wh  = (mode == 2) ? g_fwh : (z1 ? g_vwh : g_uwh);
    const __nv_bfloat16* __restrict__ Wl  = (mode == 2) ? g_fwl : (z1 ? g_vwl : g_uwl);
    const float* __restrict__ bias = z1 ? bb : ba;
    float* __restrict__ Co = (mode == 0) ? (z1 ? g_v : g_u) : Cout;

    const int n0 = blockIdx.x * 128, m0 = blockIdx.y * 128;

    __shared__ __nv_bfloat16 Ah[128 * SA], Al[128 * SA];
    __shared__ __nv_bfloat16 Bh[128 * SA], Bl[128 * SA];

    const int tid  = threadIdx.x;
    const int warp = tid >> 5, lane = tid & 31;
    const int wm = warp & 3, wn = warp >> 2;
    const int grp = lane >> 2, qd = lane & 3;
    const int l7 = lane & 7;

    const uint32_t Ah_u = (uint32_t)__cvta_generic_to_shared(Ah);
    const uint32_t Al_u = (uint32_t)__cvta_generic_to_shared(Al);
    const uint32_t Bh_u = (uint32_t)__cvta_generic_to_shared(Bh);
    const uint32_t Bl_u = (uint32_t)__cvta_generic_to_shared(Bl);
    const uint32_t a_off = ((wm * 32 + ((lane >> 3) & 1) * 8 + l7) * SA + ((lane >> 4) & 1) * 8) * 2;
    const uint32_t b_off = ((wn * 64 + ((lane >> 4) & 1) * 8 + l7) * SA + ((lane >> 3) & 1) * 8) * 2;

    float acc[2][8][4];
#pragma unroll
    for (int mi = 0; mi < 2; mi++)
#pragma unroll
        for (int ni = 0; ni < 8; ni++)
#pragma unroll
            for (int e = 0; e < 4; e++) acc[mi][ni][e] = 0.f;

    const int ldr = tid >> 2;
    const int seg = (tid & 3) * 8;

    for (int k0 = 0; k0 < CH; k0 += 32) {
#pragma unroll
        for (int p = 0; p < 2; p++) {
            int rr = ldr + p * 64;
            *(uint4*)&Ah[rr * SA + seg] = *(const uint4*)&Ahs[(size_t)(m0 + rr) * CH + k0 + seg];
            *(uint4*)&Al[rr * SA + seg] = *(const uint4*)&Als[(size_t)(m0 + rr) * CH + k0 + seg];
            *(uint4*)&Bh[rr * SA + seg] = *(const uint4*)&Wh[(size_t)(n0 + rr) * CH + k0 + seg];
            *(uint4*)&Bl[rr * SA + seg] = *(const uint4*)&Wl[(size_t)(n0 + rr) * CH + k0 + seg];
        }
        __syncthreads();
#pragma unroll
        for (int kk = 0; kk < 32; kk += 16) {
            uint32_t ah[2][4], al[2][4];
#pragma unroll
            for (int mi = 0; mi < 2; mi++) {
                ldsm_x4(ah[mi], Ah_u + a_off + (mi * 16 * SA + kk) * 2);
                ldsm_x4(al[mi], Al_u + a_off + (mi * 16 * SA + kk) * 2);
            }
#pragma unroll
            for (int nb = 0; nb < 8; nb += 4) {
                uint32_t bh4[2][4], bl4[2][4];
                ldsm_x4(bh4[0], Bh_u + b_off + (nb * 8 * SA + kk) * 2);
                ldsm_x4(bh4[1], Bh_u + b_off + ((nb + 2) * 8 * SA + kk) * 2);
                ldsm_x4(bl4[0], Bl_u + b_off + (nb * 8 * SA + kk) * 2);
                ldsm_x4(bl4[1], Bl_u + b_off + ((nb + 2) * 8 * SA + kk) * 2);
#pragma unroll
                for (int q = 0; q < 2; q++)
#pragma unroll
                    for (int mi = 0; mi < 2; mi++) {
                        mma16816(acc[mi][nb + 2 * q],     ah[mi], &bh4[q][0]);
                        mma16816(acc[mi][nb + 2 * q + 1], ah[mi], &bh4[q][2]);
                    }
#pragma unroll
                for (int q = 0; q < 2; q++)
#pragma unroll
                    for (int mi = 0; mi < 2; mi++) {
                        mma16816(acc[mi][nb + 2 * q],     ah[mi], &bl4[q][0]);
                        mma16816(acc[mi][nb + 2 * q + 1], ah[mi], &bl4[q][2]);
                    }
#pragma unroll
                for (int q = 0; q < 2; q++)
#pragma unroll
                    for (int mi = 0; mi < 2; mi++) {
                        mma16816(acc[mi][nb + 2 * q],     al[mi], &bh4[q][0]);
                        mma16816(acc[mi][nb + 2 * q + 1], al[mi], &bh4[q][2]);
                    }
            }
        }
        __syncthreads();
    }

#pragma unroll
    for (int mi = 0; mi < 2; mi++) {
        int m = m0 + wm * 32 + mi * 16 + grp;
#pragma unroll
        for (int ni = 0; ni < 8; ni++) {
            int n = n0 + wn * 64 + ni * 8 + qd * 2;
            float b0 = bias[n], b1 = bias[n + 1];
            *(float2*)(Co + (size_t)m * ncols + n) =
                make_float2(acc[mi][ni][0] + b0, acc[mi][ni][1] + b1);
            *(float2*)(Co + (size_t)(m + 8) * ncols + n) =
                make_float2(acc[mi][ni][2] + b0, acc[mi][ni][3] + b1);
        }
    }
}

// ====== K4: sparse aggregate + per-row norm + relu; writes hi/lo bf16 h ======
__global__ __launch_bounds__(128) void combine_kernel(const float* __restrict__ X)
{
    const int row = blockIdx.x, tid = threadIdx.x;
    const int warp = tid >> 5, lane = tid & 31;
    __shared__ int   nidx[16];
    __shared__ float nw[16];
    __shared__ float wred[4];
    __shared__ float mean_s, inv_s;

    const int   deg = g_deg[row];
    const float di  = g_dinv[row];
    if (tid < deg) {
        int j = g_idx[row * 16 + tid];
        nidx[tid] = j;
        nw[tid]   = di * g_dinv[j];
    }
    __syncthreads();

    const int c = tid * 4;
    float4 a = *(const float4*)&g_u[(size_t)row * CH + c];
    for (int t = 0; t < deg; t++) {
        float4 vv = *(const float4*)&g_v[(size_t)nidx[t] * CH + c];
        float w = nw[t];
        a.x = fmaf(w, vv.x, a.x); a.y = fmaf(w, vv.y, a.y);
        a.z = fmaf(w, vv.z, a.z); a.w = fmaf(w, vv.w, a.w);
    }

    float s = a.x + a.y + a.z + a.w;
#pragma unroll
    for (int o = 16; o > 0; o >>= 1) s += __shfl_xor_sync(0xffffffffu, s, o);
    if (lane == 0) wred[warp] = s;
    __syncthreads();
    if (tid == 0) mean_s = (wred[0] + wred[1] + wred[2] + wred[3]) * (1.f / CH);
    __syncthreads();
    const float mean = mean_s;

    float d0 = a.x - mean, d1 = a.y - mean, d2 = a.z - mean, d3 = a.w - mean;
    float vs = d0 * d0 + d1 * d1 + d2 * d2 + d3 * d3;
#pragma unroll
    for (int o = 16; o > 0; o >>= 1) vs += __shfl_xor_sync(0xffffffffu, vs, o);
    if (lane == 0) wred[warp] = vs;
    __syncthreads();
    if (tid == 0) inv_s = rsqrtf((wred[0] + wred[1] + wred[2] + wred[3]) * (1.f / CH) + EPSV);
    __syncthreads();
    const float inv = inv_s;

    float4 xv = *(const float4*)&X[(size_t)row * CH + c];
    float h[4];
    h[0] = fmaxf(xv.x + d0 * inv, 0.f);
    h[1] = fmaxf(xv.y + d1 * inv, 0.f);
    h[2] = fmaxf(xv.z + d2 * inv, 0.f);
    h[3] = fmaxf(xv.w + d3 * inv, 0.f);

    uint32_t hw[2], lw[2];
#pragma unroll
    for (int p = 0; p < 2; p++) {
        __nv_bfloat16 b0 = __float2bfloat16_rn(h[p * 2]);
        __nv_bfloat16 b1 = __float2bfloat16_rn(h[p * 2 + 1]);
        __nv_bfloat162 hp; hp.x = b0; hp.y = b1;
        __nv_bfloat162 lp = __floats2bfloat162_rn(h[p * 2] - __bfloat162float(b0),
                                                  h[p * 2 + 1] - __bfloat162float(b1));
        hw[p] = *(uint32_t*)&hp;
        lw[p] = *(uint32_t*)&lp;
    }
    *(uint2*)&g_hh[(size_t)row * CH + c] = make_uint2(hw[0], hw[1]);
    *(uint2*)&g_hl[(size_t)row * CH + c] = make_uint2(lw[0], lw[1]);
}

// ---------------- one-time aux stream/events (host-side; no device mem alloc) ------
namespace {
struct Aux {
    cudaStream_t s1;
    cudaEvent_t  e_split, e_uv;
    Aux() {
        cudaStreamCreateWithFlags(&s1, cudaStreamNonBlocking);
        cudaEventCreateWithFlags(&e_split, cudaEventDisableTiming);
        cudaEventCreateWithFlags(&e_uv,    cudaEventDisableTiming);
    }
};
Aux g_aux;
}

// ================= launch: fork uv onto side stream, join before combine ===========
extern "C" void kernel_launch(void* const* d_in, const int* in_sizes, int n_in,
                              void* d_out, int out_size)
{
    const float* x  = (const float*)d_in[0];
    const float* Uw = (const float*)d_in[1];
    const float* Ub = (const float*)d_in[2];
    const float* Vw = (const float*)d_in[3];
    const float* Vb = (const float*)d_in[4];
    const float* Fw = (const float*)d_in[5];
    const float* Fb = (const float*)d_in[6];
    float* out = (float*)d_out;

    // main stream: split
    split_kernel<<<2688, 256>>>(x, Uw, Vw, Fw);
    cudaEventRecord(g_aux.e_split, 0);

    // side stream: fused u,v (tensor-bound) — overlaps si+topk branch
    cudaStreamWaitEvent(g_aux.s1, g_aux.e_split, 0);
    lin_mma<<<dim3(4, 32, 2), 256, 0, g_aux.s1>>>(Ub, Vb, nullptr, CH, 0);
    cudaEventRecord(g_aux.e_uv, g_aux.s1);

    // main stream: si + topk (depends on split only)
    si_mma<<<dim3(32, 32), 256>>>();
    topk_refine<<<NPTS, 256>>>(x);

    // join: combine needs topk (main) and uv (side)
    cudaStreamWaitEvent(0, g_aux.e_uv, 0);
    combine_kernel<<<NPTS, 128>>>(x);
    lin_mma<<<dim3(2, 32, 1), 256>>>(Fb, nullptr, out, OUTF, 2); // fc
}

// round 14
// speedup vs baseline: 1.1795x; 1.0902x over previous
#include <cuda_runtime.h>
#include <cuda_bf16.h>
#include <cstdint>

#define NPTS 4096
#define CH   512
#define OUTF 256
#define EPSV 1e-5f
#define SA   40   // smem k-stride (bf16): 80B rows -> conflict-free ldmatrix

// ---------------- scratch (device-side only) ----------------
__device__ __nv_bfloat16 g_sib[(size_t)NPTS * NPTS];
__device__ float g_u [(size_t)NPTS * CH];
__device__ float g_v [(size_t)NPTS * CH];
__device__ float g_dinv[NPTS];
__device__ int   g_deg [NPTS];
__device__ int   g_idx [NPTS * 16];
__device__ __nv_bfloat16 g_xh[(size_t)NPTS * CH], g_xl[(size_t)NPTS * CH];
__device__ __nv_bfloat16 g_uwh[CH * CH],  g_uwl[CH * CH];
__device__ __nv_bfloat16 g_vwh[CH * CH],  g_vwl[CH * CH];
__device__ __nv_bfloat16 g_fwh[OUTF * CH], g_fwl[OUTF * CH];
__device__ __nv_bfloat16 g_hh[(size_t)NPTS * CH], g_hl[(size_t)NPTS * CH];

__device__ __forceinline__ void mma16816(float c[4], const uint32_t a[4], const uint32_t b[2])
{
    asm volatile(
        "mma.sync.aligned.m16n8k16.row.col.f32.bf16.bf16.f32 "
        "{%0,%1,%2,%3}, {%4,%5,%6,%7}, {%8,%9}, {%0,%1,%2,%3};"
        : "+f"(c[0]), "+f"(c[1]), "+f"(c[2]), "+f"(c[3])
        : "r"(a[0]), "r"(a[1]), "r"(a[2]), "r"(a[3]), "r"(b[0]), "r"(b[1]));
}

__device__ __forceinline__ void ldsm_x4(uint32_t r[4], uint32_t saddr)
{
    asm volatile("ldmatrix.sync.aligned.m8n8.x4.shared.b16 {%0,%1,%2,%3}, [%4];"
                 : "=r"(r[0]), "=r"(r[1]), "=r"(r[2]), "=r"(r[3]) : "r"(saddr));
}

// ================= K0: one-shot hi/lo bf16 split of x, Uw, Vw, fc_w =================
__global__ __launch_bounds__(256) void split_kernel(const float* __restrict__ X,
                                                    const float* __restrict__ Uw,
                                                    const float* __restrict__ Vw,
                                                    const float* __restrict__ Fw)
{
    size_t i = (size_t)blockIdx.x * 256 + threadIdx.x;
    const float* src; __nv_bfloat16 *dh, *dl; size_t off;
    if (i < 524288)      { src = X;  dh = g_xh;  dl = g_xl;  off = i; }
    else if (i < 589824) { src = Uw; dh = g_uwh; dl = g_uwl; off = i - 524288; }
    else if (i < 655360) { src = Vw; dh = g_vwh; dl = g_vwl; off = i - 589824; }
    else                 { src = Fw; dh = g_fwh; dl = g_fwl; off = i - 655360; }

    float4 v = ((const float4*)src)[off];
    float f[4] = {v.x, v.y, v.z, v.w};
    uint32_t hw[2], lw[2];
#pragma unroll
    for (int p = 0; p < 2; p++) {
        __nv_bfloat16 h0 = __float2bfloat16_rn(f[p * 2]);
        __nv_bfloat16 h1 = __float2bfloat16_rn(f[p * 2 + 1]);
        __nv_bfloat162 hp; hp.x = h0; hp.y = h1;
        __nv_bfloat162 lp = __floats2bfloat162_rn(f[p * 2] - __bfloat162float(h0),
                                                  f[p * 2 + 1] - __bfloat162float(h1));
        hw[p] = *(uint32_t*)&hp;
        lw[p] = *(uint32_t*)&lp;
    }
    *(uint2*)&dh[off * 4] = make_uint2(hw[0], hw[1]);
    *(uint2*)&dl[off * 4] = make_uint2(lw[0], lw[1]);
}

// ===== K1: si = xh@xh.T, upper-tri blocks + smem-transposed mirror; ldmatrix =====
__global__ __launch_bounds__(256, 2) void si_mma()
{
    const int bj = blockIdx.x, bi = blockIdx.y;
    if (bi > bj) return;
    const int m0 = bi * 128, n0 = bj * 128;

    __shared__ __align__(16) unsigned char sraw[128 * 136 * 2];
    __nv_bfloat16* As = reinterpret_cast<__nv_bfloat16*>(sraw);
    __nv_bfloat16* Bs = As + 128 * SA;
    __nv_bfloat16* Ts = reinterpret_cast<__nv_bfloat16*>(sraw);

    const int tid  = threadIdx.x;
    const int warp = tid >> 5, lane = tid & 31;
    const int wm = warp & 3, wn = warp >> 2;
    const int grp = lane >> 2, qd = lane & 3;
    const int l7 = lane & 7;

    const uint32_t As_u = (uint32_t)__cvta_generic_to_shared(As);
    const uint32_t Bs_u = (uint32_t)__cvta_generic_to_shared(Bs);
    const uint32_t a_off = ((wm * 32 + ((lane >> 3) & 1) * 8 + l7) * SA + ((lane >> 4) & 1) * 8) * 2;
    const uint32_t b_off = ((wn * 64 + ((lane >> 4) & 1) * 8 + l7) * SA + ((lane >> 3) & 1) * 8) * 2;

    float acc[2][8][4];
#pragma unroll
    for (int mi = 0; mi < 2; mi++)
#pragma unroll
        for (int ni = 0; ni < 8; ni++)
#pragma unroll
            for (int e = 0; e < 4; e++) acc[mi][ni][e] = 0.f;

    const int ldr = tid >> 2;
    const int seg = (tid & 3) * 8;

    for (int k0 = 0; k0 < CH; k0 += 32) {
#pragma unroll
        for (int p = 0; p < 2; p++) {
            int rr = ldr + p * 64;
            *(uint4*)&As[rr * SA + seg] = *(const uint4*)&g_xh[(size_t)(m0 + rr) * CH + k0 + seg];
            *(uint4*)&Bs[rr * SA + seg] = *(const uint4*)&g_xh[(size_t)(n0 + rr) * CH + k0 + seg];
        }
        __syncthreads();
#pragma unroll
        for (int kk = 0; kk < 32; kk += 16) {
            uint32_t afr[2][4];
#pragma unroll
            for (int mi = 0; mi < 2; mi++)
                ldsm_x4(afr[mi], As_u + a_off + (mi * 16 * SA + kk) * 2);
#pragma unroll
            for (int ni = 0; ni < 8; ni += 2) {
                uint32_t b4[4];
                ldsm_x4(b4, Bs_u + b_off + (ni * 8 * SA + kk) * 2);
#pragma unroll
                for (int mi = 0; mi < 2; mi++) {
                    mma16816(acc[mi][ni],     afr[mi], &b4[0]);
                    mma16816(acc[mi][ni + 1], afr[mi], &b4[2]);
                }
            }
        }
        __syncthreads();
    }

#pragma unroll
    for (int mi = 0; mi < 2; mi++) {
        int m = m0 + wm * 32 + mi * 16 + grp;
#pragma unroll
        for (int ni = 0; ni < 8; ni++) {
            int n = n0 + wn * 64 + ni * 8 + qd * 2;
            *(__nv_bfloat162*)&g_sib[(size_t)m * NPTS + n] =
                __floats2bfloat162_rn(acc[mi][ni][0], acc[mi][ni][1]);
            *(__nv_bfloat162*)&g_sib[(size_t)(m + 8) * NPTS + n] =
                __floats2bfloat162_rn(acc[mi][ni][2], acc[mi][ni][3]);
        }
    }

    if (bi != bj) {
#pragma unroll
        for (int mi = 0; mi < 2; mi++) {
            int ml = wm * 32 + mi * 16 + grp;
#pragma unroll
            for (int ni = 0; ni < 8; ni++) {
                int nl = wn * 64 + ni * 8 + qd * 2;
                Ts[nl * 136 + ml]           = __float2bfloat16_rn(acc[mi][ni][0]);
                Ts[(nl + 1) * 136 + ml]     = __float2bfloat16_rn(acc[mi][ni][1]);
                Ts[nl * 136 + ml + 8]       = __float2bfloat16_rn(acc[mi][ni][2]);
                Ts[(nl + 1) * 136 + ml + 8] = __float2bfloat16_rn(acc[mi][ni][3]);
            }
        }
        __syncthreads();
        const int r = tid >> 1, hh = (tid & 1) * 64;
#pragma unroll
        for (int i = 0; i < 8; i++) {
            *(uint4*)&g_sib[(size_t)(n0 + r) * NPTS + m0 + hh + i * 8] =
                *(const uint4*)&Ts[r * 136 + hh + i * 8];
        }
    }
}

// ================= K2: register-resident approx top-4 + margin + fp32 exact refine =====
__device__ __forceinline__ void ins4(float& v0, float& v1, float& v2, float& v3, float x)
{
    if (x > v3) {
        if (x > v1) {
            if (x > v0) { v3 = v2; v2 = v1; v1 = v0; v0 = x; }
            else        { v3 = v2; v2 = v1; v1 = x; }
        } else {
            if (x > v2) { v3 = v2; v2 = x; }
            else        { v3 = x; }
        }
    }
}

#define TOPK_MARGIN 4.0f

__global__ __launch_bounds__(256) void topk_refine(const float* __restrict__ X)
{
    const int row = blockIdx.x;
    const int tid = threadIdx.x;
    const int warp = tid >> 5, lane = tid & 31;
    const uint4* __restrict__ s4 = (const uint4*)(g_sib + (size_t)row * NPTS);

    __shared__ float xr[CH];
    __shared__ float wtop[8][4];
    __shared__ float ex[32];
    __shared__ int   cand[32];
    __shared__ int   cnt;
    __shared__ float thr_s;

    xr[tid]       = X[(size_t)row * CH + tid];
    xr[tid + 256] = X[(size_t)row * CH + tid + 256];
    if (tid == 0) cnt = 0;

    // phase 1: per-thread top-4 over 16 register-resident bf16 values
    uint4 u0 = s4[tid];
    uint4 u1 = s4[tid + 256];
    float v0 = -1e30f, v1 = -1e30f, v2 = -1e30f, v3 = -1e30f;
    {
        uint32_t w[8] = {u0.x, u0.y, u0.z, u0.w, u1.x, u1.y, u1.z, u1.w};
#pragma unroll
        for (int t = 0; t < 8; t++) {
            __nv_bfloat162 p = *(__nv_bfloat162*)&w[t];
            ins4(v0, v1, v2, v3, __bfloat162float(p.x));
            ins4(v0, v1, v2, v3, __bfloat162float(p.y));
        }
    }

    // warp butterfly merge of sorted-4 lists (no smem, no barriers)
#pragma unroll
    for (int o = 16; o > 0; o >>= 1) {
        float o0 = __shfl_xor_sync(0xffffffffu, v0, o);
        float o1 = __shfl_xor_sync(0xffffffffu, v1, o);
        float o2 = __shfl_xor_sync(0xffffffffu, v2, o);
        float o3 = __shfl_xor_sync(0xffffffffu, v3, o);
        ins4(v0, v1, v2, v3, o0);
        ins4(v0, v1, v2, v3, o1);
        ins4(v0, v1, v2, v3, o2);
        ins4(v0, v1, v2, v3, o3);
    }
    if (lane == 0) { wtop[warp][0] = v0; wtop[warp][1] = v1; wtop[warp][2] = v2; wtop[warp][3] = v3; }
    __syncthreads();

    // warp 0: merge 8x4 values -> block approx top-4; thr = 4th - margin
    if (warp == 0) {
        float b0 = ((const float*)wtop)[lane];
        float w0 = b0, w1 = -1e30f, w2 = -1e30f, w3 = -1e30f;
#pragma unroll
        for (int o = 16; o > 0; o >>= 1) {
            float o0 = __shfl_xor_sync(0xffffffffu, w0, o);
            float o1 = __shfl_xor_sync(0xffffffffu, w1, o);
            float o2 = __shfl_xor_sync(0xffffffffu, w2, o);
            float o3 = __shfl_xor_sync(0xffffffffu, w3, o);
            ins4(w0, w1, w2, w3, o0);
            ins4(w0, w1, w2, w3, o1);
            ins4(w0, w1, w2, w3, o2);
            ins4(w0, w1, w2, w3, o3);
        }
        if (lane == 0) thr_s = w3 - TOPK_MARGIN;
    }
    __syncthreads();
    const float thr = thr_s;

    // phase 2: candidate collection from REGISTERS (no second global read)
    // u0 covers elements [tid*8, tid*8+8); u1 covers [(tid+256)*8, (tid+256)*8+8)
    {
        uint32_t w[8] = {u0.x, u0.y, u0.z, u0.w, u1.x, u1.y, u1.z, u1.w};
#pragma unroll
        for (int t = 0; t < 8; t++) {
            __nv_bfloat162 p = *(__nv_bfloat162*)&w[t];
            int base = (t < 4 ? tid * 8 : (tid + 256) * 8 - 8) + t * 2;
            if (__bfloat162float(p.x) >= thr) {
                int pi = atomicAdd(&cnt, 1);
                if (pi < 32) cand[pi] = base;
            }
            if (__bfloat162float(p.y) >= thr) {
                int pi = atomicAdd(&cnt, 1);
                if (pi < 32) cand[pi] = base + 1;
            }
        }
    }
    __syncthreads();
    const int cn = min(cnt, 32);

    // exact fp32 dot per candidate (warp per candidate)
    for (int c = warp; c < cn; c += 8) {
        const float* __restrict__ xc = X + (size_t)cand[c] * CH;
        float sum = 0.f;
        for (int k = lane; k < CH; k += 32) sum = fmaf(xr[k], xc[k], sum);
#pragma unroll
        for (int o = 16; o > 0; o >>= 1) sum += __shfl_xor_sync(0xffffffffu, sum, o);
        if (lane == 0) ex[c] = sum;
    }
    __syncthreads();

    if (tid == 0) {
        float tmp[32];
        for (int c = 0; c < cn; c++) tmp[c] = ex[c];
        float t4 = -1e30f;
        for (int p = 0; p < 4; p++) {
            int bidx = 0; float bv = -1e30f;
            for (int c = 0; c < cn; c++) if (tmp[c] > bv) { bv = tmp[c]; bidx = c; }
            t4 = bv; tmp[bidx] = -1e30f;
        }
        int d = 0;
        for (int c = 0; c < cn; c++) {
            if (ex[c] >= t4) { if (d < 16) g_idx[row * 16 + d] = cand[c]; d++; }
        }
        g_deg[row]  = min(d, 16);
        g_dinv[row] = rsqrtf((float)d);
    }
}

// ======== split-bf16 linear, 128x128, ldmatrix; product-major MMA ordering ========
__global__ __launch_bounds__(256, 2) void lin_mma(const float* __restrict__ ba,
                                                  const float* __restrict__ bb,
                                                  float* __restrict__ Cout,
                                                  int ncols, int mode)
{
    const bool z1 = (mode == 0) && (blockIdx.z == 1);
    const __nv_bfloat16* __restrict__ Ahs = (mode == 2) ? g_hh : g_xh;
    const __nv_bfloat16* __restrict__ Als = (mode == 2) ? g_hl : g_xl;
    const __nv_bfloat16* __restrict__ Wh  = (mode == 2) ? g_fwh : (z1 ? g_vwh : g_uwh);
    const __nv_bfloat16* __restrict__ Wl  = (mode == 2) ? g_fwl : (z1 ? g_vwl : g_uwl);
    const float* __restrict__ bias = z1 ? bb : ba;
    float* __restrict__ Co = (mode == 0) ? (z1 ? g_v : g_u) : Cout;

    const int n0 = blockIdx.x * 128, m0 = blockIdx.y * 128;

    __shared__ __nv_bfloat16 Ah[128 * SA], Al[128 * SA];
    __shared__ __nv_bfloat16 Bh[128 * SA], Bl[128 * SA];

    const int tid  = threadIdx.x;
    const int warp = tid >> 5, lane = tid & 31;
    const int wm = warp & 3, wn = warp >> 2;
    const int grp = lane >> 2, qd = lane & 3;
    const int l7 = lane & 7;

    const uint32_t Ah_u = (uint32_t)__cvta_generic_to_shared(Ah);
    const uint32_t Al_u = (uint32_t)__cvta_generic_to_shared(Al);
    const uint32_t Bh_u = (uint32_t)__cvta_generic_to_shared(Bh);
    const uint32_t Bl_u = (uint32_t)__cvta_generic_to_shared(Bl);
    const uint32_t a_off = ((wm * 32 + ((lane >> 3) & 1) * 8 + l7) * SA + ((lane >> 4) & 1) * 8) * 2;
    const uint32_t b_off = ((wn * 64 + ((lane >> 4) & 1) * 8 + l7) * SA + ((lane >> 3) & 1) * 8) * 2;

    float acc[2][8][4];
#pragma unroll
    for (int mi = 0; mi < 2; mi++)
#pragma unroll
        for (int ni = 0; ni < 8; ni++)
#pragma unroll
            for (int e = 0; e < 4; e++) acc[mi][ni][e] = 0.f;

    const int ldr = tid >> 2;
    const int seg = (tid & 3) * 8;

    for (int k0 = 0; k0 < CH; k0 += 32) {
#pragma unroll
        for (int p = 0; p < 2; p++) {
            int rr = ldr + p * 64;
            *(uint4*)&Ah[rr * SA + seg] = *(const uint4*)&Ahs[(size_t)(m0 + rr) * CH + k0 + seg];
            *(uint4*)&Al[rr * SA + seg] = *(const uint4*)&Als[(size_t)(m0 + rr) * CH + k0 + seg];
            *(uint4*)&Bh[rr * SA + seg] = *(const uint4*)&Wh[(size_t)(n0 + rr) * CH + k0 + seg];
            *(uint4*)&Bl[rr * SA + seg] = *(const uint4*)&Wl[(size_t)(n0 + rr) * CH + k0 + seg];
        }
        __syncthreads();
#pragma unroll
        for (int kk = 0; kk < 32; kk += 16) {
            uint32_t ah[2][4], al[2][4];
#pragma unroll
            for (int mi = 0; mi < 2; mi++) {
                ldsm_x4(ah[mi], Ah_u + a_off + (mi * 16 * SA + kk) * 2);
                ldsm_x4(al[mi], Al_u + a_off + (mi * 16 * SA + kk) * 2);
            }
#pragma unroll
            for (int nb = 0; nb < 8; nb += 4) {
                uint32_t bh4[2][4], bl4[2][4];
                ldsm_x4(bh4[0], Bh_u + b_off + (nb * 8 * SA + kk) * 2);
                ldsm_x4(bh4[1], Bh_u + b_off + ((nb + 2) * 8 * SA + kk) * 2);
                ldsm_x4(bl4[0], Bl_u + b_off + (nb * 8 * SA + kk) * 2);
                ldsm_x4(bl4[1], Bl_u + b_off + ((nb + 2) * 8 * SA + kk) * 2);
#pragma unroll
                for (int q = 0; q < 2; q++)
#pragma unroll
                    for (int mi = 0; mi < 2; mi++) {
                        mma16816(acc[mi][nb + 2 * q],     ah[mi], &bh4[q][0]);
                        mma16816(acc[mi][nb + 2 * q + 1], ah[mi], &bh4[q][2]);
                    }
#pragma unroll
                for (int q = 0; q < 2; q++)
#pragma unroll
                    for (int mi = 0; mi < 2; mi++) {
                        mma16816(acc[mi][nb + 2 * q],     ah[mi], &bl4[q][0]);
                        mma16816(acc[mi][nb + 2 * q + 1], ah[mi], &bl4[q][2]);
                    }
#pragma unroll
                for (int q = 0; q < 2; q++)
#pragma unroll
                    for (int mi = 0; mi < 2; mi++) {
                        mma16816(acc[mi][nb + 2 * q],     al[mi], &bh4[q][0]);
                        mma16816(acc[mi][nb + 2 * q + 1], al[mi], &bh4[q][2]);
                    }
            }
        }
        __syncthreads();
    }

#pragma unroll
    for (int mi = 0; mi < 2; mi++) {
        int m = m0 + wm * 32 + mi * 16 + grp;
#pragma unroll
        for (int ni = 0; ni < 8; ni++) {
            int n = n0 + wn * 64 + ni * 8 + qd * 2;
            float b0 = bias[n], b1 = bias[n + 1];
            *(float2*)(Co + (size_t)m * ncols + n) =
                make_float2(acc[mi][ni][0] + b0, acc[mi][ni][1] + b1);
            *(float2*)(Co + (size_t)(m + 8) * ncols + n) =
                make_float2(acc[mi][ni][2] + b0, acc[mi][ni][3] + b1);
        }
    }
}

// ====== K4: sparse aggregate + per-row norm + relu; writes hi/lo bf16 h ======
__global__ __launch_bounds__(128) void combine_kernel(const float* __restrict__ X)
{
    const int row = blockIdx.x, tid = threadIdx.x;
    const int warp = tid >> 5, lane = tid & 31;
    __shared__ int   nidx[16];
    __shared__ float nw[16];
    __shared__ float wred[4];
    __shared__ float mean_s, inv_s;

    const int   deg = g_deg[row];
    const float di  = g_dinv[row];
    if (tid < deg) {
        int j = g_idx[row * 16 + tid];
        nidx[tid] = j;
        nw[tid]   = di * g_dinv[j];
    }
    __syncthreads();

    const int c = tid * 4;
    float4 a = *(const float4*)&g_u[(size_t)row * CH + c];
    for (int t = 0; t < deg; t++) {
        float4 vv = *(const float4*)&g_v[(size_t)nidx[t] * CH + c];
        float w = nw[t];
        a.x = fmaf(w, vv.x, a.x); a.y = fmaf(w, vv.y, a.y);
        a.z = fmaf(w, vv.z, a.z); a.w = fmaf(w, vv.w, a.w);
    }

    float s = a.x + a.y + a.z + a.w;
#pragma unroll
    for (int o = 16; o > 0; o >>= 1) s += __shfl_xor_sync(0xffffffffu, s, o);
    if (lane == 0) wred[warp] = s;
    __syncthreads();
    if (tid == 0) mean_s = (wred[0] + wred[1] + wred[2] + wred[3]) * (1.f / CH);
    __syncthreads();
    const float mean = mean_s;

    float d0 = a.x - mean, d1 = a.y - mean, d2 = a.z - mean, d3 = a.w - mean;
    float vs = d0 * d0 + d1 * d1 + d2 * d2 + d3 * d3;
#pragma unroll
    for (int o = 16; o > 0; o >>= 1) vs += __shfl_xor_sync(0xffffffffu, vs, o);
    if (lane == 0) wred[warp] = vs;
    __syncthreads();
    if (tid == 0) inv_s = rsqrtf((wred[0] + wred[1] + wred[2] + wred[3]) * (1.f / CH) + EPSV);
    __syncthreads();
    const float inv = inv_s;

    float4 xv = *(const float4*)&X[(size_t)row * CH + c];
    float h[4];
    h[0] = fmaxf(xv.x + d0 * inv, 0.f);
    h[1] = fmaxf(xv.y + d1 * inv, 0.f);
    h[2] = fmaxf(xv.z + d2 * inv, 0.f);
    h[3] = fmaxf(xv.w + d3 * inv, 0.f);

    uint32_t hw[2], lw[2];
#pragma unroll
    for (int p = 0; p < 2; p++) {
        __nv_bfloat16 b0 = __float2bfloat16_rn(h[p * 2]);
        __nv_bfloat16 b1 = __float2bfloat16_rn(h[p * 2 + 1]);
        __nv_bfloat162 hp; hp.x = b0; hp.y = b1;
        __nv_bfloat162 lp = __floats2bfloat162_rn(h[p * 2] - __bfloat162float(b0),
                                                  h[p * 2 + 1] - __bfloat162float(b1));
        hw[p] = *(uint32_t*)&hp;
        lw[p] = *(uint32_t*)&lp;
    }
    *(uint2*)&g_hh[(size_t)row * CH + c] = make_uint2(hw[0], hw[1]);
    *(uint2*)&g_hl[(size_t)row * CH + c] = make_uint2(lw[0], lw[1]);
}

// ---------------- one-time aux stream/events (host-side; no device mem alloc) ------
namespace {
struct Aux {
    cudaStream_t s1;
    cudaEvent_t  e_split, e_uv;
    Aux() {
        cudaStreamCreateWithFlags(&s1, cudaStreamNonBlocking);
        cudaEventCreateWithFlags(&e_split, cudaEventDisableTiming);
        cudaEventCreateWithFlags(&e_uv,    cudaEventDisableTiming);
    }
};
Aux g_aux;
}

// ================= launch: fork uv onto side stream, join before combine ===========
extern "C" void kernel_launch(void* const* d_in, const int* in_sizes, int n_in,
                              void* d_out, int out_size)
{
    const float* x  = (const float*)d_in[0];
    const float* Uw = (const float*)d_in[1];
    const float* Ub = (const float*)d_in[2];
    const float* Vw = (const float*)d_in[3];
    const float* Vb = (const float*)d_in[4];
    const float* Fw = (const float*)d_in[5];
    const float* Fb = (const float*)d_in[6];
    float* out = (float*)d_out;

    // main stream: split
    split_kernel<<<2688, 256>>>(x, Uw, Vw, Fw);
    cudaEventRecord(g_aux.e_split, 0);

    // side stream: fused u,v (tensor-bound) — overlaps si+topk branch
    cudaStreamWaitEvent(g_aux.s1, g_aux.e_split, 0);
    lin_mma<<<dim3(4, 32, 2), 256, 0, g_aux.s1>>>(Ub, Vb, nullptr, CH, 0);
    cudaEventRecord(g_aux.e_uv, g_aux.s1);

    // main stream: si + topk (depends on split only)
    si_mma<<<dim3(32, 32), 256>>>();
    topk_refine<<<NPTS, 256>>>(x);

    // join: combine needs topk (main) and uv (side)
    cudaStreamWaitEvent(0, g_aux.e_uv, 0);
    combine_kernel<<<NPTS, 128>>>(x);
    lin_mma<<<dim3(2, 32, 1), 256>>>(Fb, nullptr, out, OUTF, 2); // fc
}

// round 15
// speedup vs baseline: 1.2235x; 1.0372x over previous
#include <cuda_runtime.h>
#include <cuda_bf16.h>
#include <cstdint>

#define NPTS 4096
#define CH   512
#define OUTF 256
#define EPSV 1e-5f
#define SA   40   // smem k-stride (bf16): 80B rows -> conflict-free ldmatrix

// ---------------- scratch (device-side only) ----------------
__device__ __nv_bfloat16 g_sib[(size_t)NPTS * NPTS];
__device__ float g_u [(size_t)NPTS * CH];
__device__ float g_v [(size_t)NPTS * CH];
__device__ float g_dinv[NPTS];
__device__ int   g_deg [NPTS];
__device__ int   g_idx [NPTS * 16];
__device__ __nv_bfloat16 g_xh[(size_t)NPTS * CH], g_xl[(size_t)NPTS * CH];
__device__ __nv_bfloat16 g_uwh[CH * CH],  g_uwl[CH * CH];
__device__ __nv_bfloat16 g_vwh[CH * CH],  g_vwl[CH * CH];
__device__ __nv_bfloat16 g_fwh[OUTF * CH], g_fwl[OUTF * CH];
__device__ __nv_bfloat16 g_hh[(size_t)NPTS * CH], g_hl[(size_t)NPTS * CH];

__device__ __forceinline__ void mma16816(float c[4], const uint32_t a[4], const uint32_t b[2])
{
    asm volatile(
        "mma.sync.aligned.m16n8k16.row.col.f32.bf16.bf16.f32 "
        "{%0,%1,%2,%3}, {%4,%5,%6,%7}, {%8,%9}, {%0,%1,%2,%3};"
        : "+f"(c[0]), "+f"(c[1]), "+f"(c[2]), "+f"(c[3])
        : "r"(a[0]), "r"(a[1]), "r"(a[2]), "r"(a[3]), "r"(b[0]), "r"(b[1]));
}

__device__ __forceinline__ void ldsm_x4(uint32_t r[4], uint32_t saddr)
{
    asm volatile("ldmatrix.sync.aligned.m8n8.x4.shared.b16 {%0,%1,%2,%3}, [%4];"
                 : "=r"(r[0]), "=r"(r[1]), "=r"(r[2]), "=r"(r[3]) : "r"(saddr));
}

// ================= K0: one-shot hi/lo bf16 split of x, Uw, Vw, fc_w =================
__global__ __launch_bounds__(256) void split_kernel(const float* __restrict__ X,
                                                    const float* __restrict__ Uw,
                                                    const float* __restrict__ Vw,
                                                    const float* __restrict__ Fw)
{
    size_t i = (size_t)blockIdx.x * 256 + threadIdx.x;
    const float* src; __nv_bfloat16 *dh, *dl; size_t off;
    if (i < 524288)      { src = X;  dh = g_xh;  dl = g_xl;  off = i; }
    else if (i < 589824) { src = Uw; dh = g_uwh; dl = g_uwl; off = i - 524288; }
    else if (i < 655360) { src = Vw; dh = g_vwh; dl = g_vwl; off = i - 589824; }
    else                 { src = Fw; dh = g_fwh; dl = g_fwl; off = i - 655360; }

    float4 v = ((const float4*)src)[off];
    float f[4] = {v.x, v.y, v.z, v.w};
    uint32_t hw[2], lw[2];
#pragma unroll
    for (int p = 0; p < 2; p++) {
        __nv_bfloat16 h0 = __float2bfloat16_rn(f[p * 2]);
        __nv_bfloat16 h1 = __float2bfloat16_rn(f[p * 2 + 1]);
        __nv_bfloat162 hp; hp.x = h0; hp.y = h1;
        __nv_bfloat162 lp = __floats2bfloat162_rn(f[p * 2] - __bfloat162float(h0),
                                                  f[p * 2 + 1] - __bfloat162float(h1));
        hw[p] = *(uint32_t*)&hp;
        lw[p] = *(uint32_t*)&lp;
    }
    *(uint2*)&dh[off * 4] = make_uint2(hw[0], hw[1]);
    *(uint2*)&dl[off * 4] = make_uint2(lw[0], lw[1]);
}

// ===== K1: si = xh@xh.T, upper-tri blocks + smem-transposed mirror; ldmatrix =====
__global__ __launch_bounds__(256, 2) void si_mma()
{
    const int bj = blockIdx.x, bi = blockIdx.y;
    if (bi > bj) return;
    const int m0 = bi * 128, n0 = bj * 128;

    __shared__ __align__(16) unsigned char sraw[128 * 136 * 2];
    __nv_bfloat16* As = reinterpret_cast<__nv_bfloat16*>(sraw);
    __nv_bfloat16* Bs = As + 128 * SA;
    __nv_bfloat16* Ts = reinterpret_cast<__nv_bfloat16*>(sraw);

    const int tid  = threadIdx.x;
    const int warp = tid >> 5, lane = tid & 31;
    const int wm = warp & 3, wn = warp >> 2;
    const int grp = lane >> 2, qd = lane & 3;
    const int l7 = lane & 7;

    const uint32_t As_u = (uint32_t)__cvta_generic_to_shared(As);
    const uint32_t Bs_u = (uint32_t)__cvta_generic_to_shared(Bs);
    const uint32_t a_off = ((wm * 32 + ((lane >> 3) & 1) * 8 + l7) * SA + ((lane >> 4) & 1) * 8) * 2;
    const uint32_t b_off = ((wn * 64 + ((lane >> 4) & 1) * 8 + l7) * SA + ((lane >> 3) & 1) * 8) * 2;

    float acc[2][8][4];
#pragma unroll
    for (int mi = 0; mi < 2; mi++)
#pragma unroll
        for (int ni = 0; ni < 8; ni++)
#pragma unroll
            for (int e = 0; e < 4; e++) acc[mi][ni][e] = 0.f;

    const int ldr = tid >> 2;
    const int seg = (tid & 3) * 8;

    for (int k0 = 0; k0 < CH; k0 += 32) {
#pragma unroll
        for (int p = 0; p < 2; p++) {
            int rr = ldr + p * 64;
            *(uint4*)&As[rr * SA + seg] = *(const uint4*)&g_xh[(size_t)(m0 + rr) * CH + k0 + seg];
            *(uint4*)&Bs[rr * SA + seg] = *(const uint4*)&g_xh[(size_t)(n0 + rr) * CH + k0 + seg];
        }
        __syncthreads();
#pragma unroll
        for (int kk = 0; kk < 32; kk += 16) {
            uint32_t afr[2][4];
#pragma unroll
            for (int mi = 0; mi < 2; mi++)
                ldsm_x4(afr[mi], As_u + a_off + (mi * 16 * SA + kk) * 2);
#pragma unroll
            for (int ni = 0; ni < 8; ni += 2) {
                uint32_t b4[4];
                ldsm_x4(b4, Bs_u + b_off + (ni * 8 * SA + kk) * 2);
#pragma unroll
                for (int mi = 0; mi < 2; mi++) {
                    mma16816(acc[mi][ni],     afr[mi], &b4[0]);
                    mma16816(acc[mi][ni + 1], afr[mi], &b4[2]);
                }
            }
        }
        __syncthreads();
    }

#pragma unroll
    for (int mi = 0; mi < 2; mi++) {
        int m = m0 + wm * 32 + mi * 16 + grp;
#pragma unroll
        for (int ni = 0; ni < 8; ni++) {
            int n = n0 + wn * 64 + ni * 8 + qd * 2;
            *(__nv_bfloat162*)&g_sib[(size_t)m * NPTS + n] =
                __floats2bfloat162_rn(acc[mi][ni][0], acc[mi][ni][1]);
            *(__nv_bfloat162*)&g_sib[(size_t)(m + 8) * NPTS + n] =
                __floats2bfloat162_rn(acc[mi][ni][2], acc[mi][ni][3]);
        }
    }

    if (bi != bj) {
#pragma unroll
        for (int mi = 0; mi < 2; mi++) {
            int ml = wm * 32 + mi * 16 + grp;
#pragma unroll
            for (int ni = 0; ni < 8; ni++) {
                int nl = wn * 64 + ni * 8 + qd * 2;
                Ts[nl * 136 + ml]           = __float2bfloat16_rn(acc[mi][ni][0]);
                Ts[(nl + 1) * 136 + ml]     = __float2bfloat16_rn(acc[mi][ni][1]);
                Ts[nl * 136 + ml + 8]       = __float2bfloat16_rn(acc[mi][ni][2]);
                Ts[(nl + 1) * 136 + ml + 8] = __float2bfloat16_rn(acc[mi][ni][3]);
            }
        }
        __syncthreads();
        const int r = tid >> 1, hh = (tid & 1) * 64;
#pragma unroll
        for (int i = 0; i < 8; i++) {
            *(uint4*)&g_sib[(size_t)(n0 + r) * NPTS + m0 + hh + i * 8] =
                *(const uint4*)&Ts[r * 136 + hh + i * 8];
        }
    }
}

// ======= K2: hmax2-tree prescreen + approx top-4 (margin) + fp32 exact refine =======
__device__ __forceinline__ void ins4(float& v0, float& v1, float& v2, float& v3, float x)
{
    if (x > v3) {
        if (x > v1) {
            if (x > v0) { v3 = v2; v2 = v1; v1 = v0; v0 = x; }
            else        { v3 = v2; v2 = v1; v1 = x; }
        } else {
            if (x > v2) { v3 = v2; v2 = x; }
            else        { v3 = x; }
        }
    }
}

#define TOPK_MARGIN 4.0f

__global__ __launch_bounds__(256) void topk_refine(const float* __restrict__ X)
{
    const int row = blockIdx.x;
    const int tid = threadIdx.x;
    const int warp = tid >> 5, lane = tid & 31;
    const uint4* __restrict__ s4 = (const uint4*)(g_sib + (size_t)row * NPTS);

    __shared__ float xr[CH];
    __shared__ float wtop[8][4];
    __shared__ float ex[32];
    __shared__ int   cand[32];
    __shared__ int   cnt;
    __shared__ float thr_s;

    xr[tid]       = X[(size_t)row * CH + tid];
    xr[tid + 256] = X[(size_t)row * CH + tid + 256];
    if (tid == 0) cnt = 0;

    // phase 1: packed hmax2 tree over 16 register-resident bf16 values
    uint4 u0 = s4[tid];
    uint4 u1 = s4[tid + 256];
    __nv_bfloat162 p0 = __hmax2(*(__nv_bfloat162*)&u0.x, *(__nv_bfloat162*)&u0.y);
    __nv_bfloat162 p1 = __hmax2(*(__nv_bfloat162*)&u0.z, *(__nv_bfloat162*)&u0.w);
    __nv_bfloat162 p2 = __hmax2(*(__nv_bfloat162*)&u1.x, *(__nv_bfloat162*)&u1.y);
    __nv_bfloat162 p3 = __hmax2(*(__nv_bfloat162*)&u1.z, *(__nv_bfloat162*)&u1.w);
    __nv_bfloat162 pm = __hmax2(__hmax2(p0, p1), __hmax2(p2, p3));
    const float e = __bfloat162float(pm.x);   // max of even positions
    const float o = __bfloat162float(pm.y);   // max of odd positions
    const float tmax = fmaxf(e, o);

    // warp butterfly top-4 merge (2 real values per thread; subset => thr safe)
    float v0 = tmax, v1 = fminf(e, o), v2 = -1e30f, v3 = -1e30f;
#pragma unroll
    for (int of = 16; of > 0; of >>= 1) {
        float o0 = __shfl_xor_sync(0xffffffffu, v0, of);
        float o1 = __shfl_xor_sync(0xffffffffu, v1, of);
        float o2 = __shfl_xor_sync(0xffffffffu, v2, of);
        float o3 = __shfl_xor_sync(0xffffffffu, v3, of);
        ins4(v0, v1, v2, v3, o0);
        ins4(v0, v1, v2, v3, o1);
        ins4(v0, v1, v2, v3, o2);
        ins4(v0, v1, v2, v3, o3);
    }
    if (lane == 0) { wtop[warp][0] = v0; wtop[warp][1] = v1; wtop[warp][2] = v2; wtop[warp][3] = v3; }
    __syncthreads();

    // warp 0: merge 8x4 values -> block approx top-4; thr = 4th - margin
    if (warp == 0) {
        float b0 = ((const float*)wtop)[lane];
        float w0 = b0, w1 = -1e30f, w2 = -1e30f, w3 = -1e30f;
#pragma unroll
        for (int of = 16; of > 0; of >>= 1) {
            float o0 = __shfl_xor_sync(0xffffffffu, w0, of);
            float o1 = __shfl_xor_sync(0xffffffffu, w1, of);
            float o2 = __shfl_xor_sync(0xffffffffu, w2, of);
            float o3 = __shfl_xor_sync(0xffffffffu, w3, of);
            ins4(w0, w1, w2, w3, o0);
            ins4(w0, w1, w2, w3, o1);
            ins4(w0, w1, w2, w3, o2);
            ins4(w0, w1, w2, w3, o3);
        }
        if (lane == 0) thr_s = w3 - TOPK_MARGIN;
    }
    __syncthreads();
    const float thr = thr_s;

    // phase 2: candidate collection from registers, gated on thread max
    if (tmax >= thr) {
        uint32_t w[8] = {u0.x, u0.y, u0.z, u0.w, u1.x, u1.y, u1.z, u1.w};
#pragma unroll
        for (int t = 0; t < 8; t++) {
            __nv_bfloat162 p = *(__nv_bfloat162*)&w[t];
            int base = (t < 4 ? tid * 8 : (tid + 256) * 8 - 8) + t * 2;
            if (__bfloat162float(p.x) >= thr) {
                int pi = atomicAdd(&cnt, 1);
                if (pi < 32) cand[pi] = base;
            }
            if (__bfloat162float(p.y) >= thr) {
                int pi = atomicAdd(&cnt, 1);
                if (pi < 32) cand[pi] = base + 1;
            }
        }
    }
    __syncthreads();
    const int cn = min(cnt, 32);

    // exact fp32 dot per candidate (warp per candidate)
    for (int c = warp; c < cn; c += 8) {
        const float* __restrict__ xc = X + (size_t)cand[c] * CH;
        float sum = 0.f;
        for (int k = lane; k < CH; k += 32) sum = fmaf(xr[k], xc[k], sum);
#pragma unroll
        for (int of = 16; of > 0; of >>= 1) sum += __shfl_xor_sync(0xffffffffu, sum, of);
        if (lane == 0) ex[c] = sum;
    }
    __syncthreads();

    if (tid == 0) {
        float tmp[32];
        for (int c = 0; c < cn; c++) tmp[c] = ex[c];
        float t4 = -1e30f;
        for (int p = 0; p < 4; p++) {
            int bidx = 0; float bv = -1e30f;
            for (int c = 0; c < cn; c++) if (tmp[c] > bv) { bv = tmp[c]; bidx = c; }
            t4 = bv; tmp[bidx] = -1e30f;
        }
        int d = 0;
        for (int c = 0; c < cn; c++) {
            if (ex[c] >= t4) { if (d < 16) g_idx[row * 16 + d] = cand[c]; d++; }
        }
        g_deg[row]  = min(d, 16);
        g_dinv[row] = rsqrtf((float)d);
    }
}

// ======== split-bf16 linear, 128x128, ldmatrix; product-major MMA ordering ========
__global__ __launch_bounds__(256, 2) void lin_mma(const float* __restrict__ ba,
                                                  const float* __restrict__ bb,
                                                  float* __restrict__ Cout,
                                                  int ncols, int mode)
{
    const bool z1 = (mode == 0) && (blockIdx.z == 1);
    const __nv_bfloat16* __restrict__ Ahs = (mode == 2) ? g_hh : g_xh;
    const __nv_bfloat16* __restrict__ Als = (mode == 2) ? g_hl : g_xl;
    const __nv_bfloat16* __restrict__ Wh  = (mode == 2) ? g_fwh : (z1 ? g_vwh : g_uwh);
    const __nv_bfloat16* __restrict__ Wl  = (mode == 2) ? g_fwl : (z1 ? g_vwl : g_uwl);
    const float* __restrict__ bias = z1 ? bb : ba;
    float* __restrict__ Co = (mode == 0) ? (z1 ? g_v : g_u) : Cout;

    const int n0 = blockIdx.x * 128, m0 = blockIdx.y * 128;

    __shared__ __nv_bfloat16 Ah[128 * SA], Al[128 * SA];
    __shared__ __nv_bfloat16 Bh[128 * SA], Bl[128 * SA];

    const int tid  = threadIdx.x;
    const int warp = tid >> 5, lane = tid & 31;
    const int wm = warp & 3, wn = warp >> 2;
    const int grp = lane >> 2, qd = lane & 3;
    const int l7 = lane & 7;

    const uint32_t Ah_u = (uint32_t)__cvta_generic_to_shared(Ah);
    const uint32_t Al_u = (uint32_t)__cvta_generic_to_shared(Al);
    const uint32_t Bh_u = (uint32_t)__cvta_generic_to_shared(Bh);
    const uint32_t Bl_u = (uint32_t)__cvta_generic_to_shared(Bl);
    const uint32_t a_off = ((wm * 32 + ((lane >> 3) & 1) * 8 + l7) * SA + ((lane >> 4) & 1) * 8) * 2;
    const uint32_t b_off = ((wn * 64 + ((lane >> 4) & 1) * 8 + l7) * SA + ((lane >> 3) & 1) * 8) * 2;

    float acc[2][8][4];
#pragma unroll
    for (int mi = 0; mi < 2; mi++)
#pragma unroll
        for (int ni = 0; ni < 8; ni++)
#pragma unroll
            for (int e = 0; e < 4; e++) acc[mi][ni][e] = 0.f;

    const int ldr = tid >> 2;
    const int seg = (tid & 3) * 8;

    for (int k0 = 0; k0 < CH; k0 += 32) {
#pragma unroll
        for (int p = 0; p < 2; p++) {
            int rr = ldr + p * 64;
            *(uint4*)&Ah[rr * SA + seg] = *(const uint4*)&Ahs[(size_t)(m0 + rr) * CH + k0 + seg];
            *(uint4*)&Al[rr * SA + seg] = *(const uint4*)&Als[(size_t)(m0 + rr) * CH + k0 + seg];
            *(uint4*)&Bh[rr * SA + seg] = *(const uint4*)&Wh[(size_t)(n0 + rr) * CH + k0 + seg];
            *(uint4*)&Bl[rr * SA + seg] = *(const uint4*)&Wl[(size_t)(n0 + rr) * CH + k0 + seg];
        }
        __syncthreads();
#pragma unroll
        for (int kk = 0; kk < 32; kk += 16) {
            uint32_t ah[2][4], al[2][4];
#pragma unroll
            for (int mi = 0; mi < 2; mi++) {
                ldsm_x4(ah[mi], Ah_u + a_off + (mi * 16 * SA + kk) * 2);
                ldsm_x4(al[mi], Al_u + a_off + (mi * 16 * SA + kk) * 2);
            }
#pragma unroll
            for (int nb = 0; nb < 8; nb += 4) {
                uint32_t bh4[2][4], bl4[2][4];
                ldsm_x4(bh4[0], Bh_u + b_off + (nb * 8 * SA + kk) * 2);
                ldsm_x4(bh4[1], Bh_u + b_off + ((nb + 2) * 8 * SA + kk) * 2);
                ldsm_x4(bl4[0], Bl_u + b_off + (nb * 8 * SA + kk) * 2);
                ldsm_x4(bl4[1], Bl_u + b_off + ((nb + 2) * 8 * SA + kk) * 2);
#pragma unroll
                for (int q = 0; q < 2; q++)
#pragma unroll
                    for (int mi = 0; mi < 2; mi++) {
                        mma16816(acc[mi][nb + 2 * q],     ah[mi], &bh4[q][0]);
                        mma16816(acc[mi][nb + 2 * q + 1], ah[mi], &bh4[q][2]);
                    }
#pragma unroll
                for (int q = 0; q < 2; q++)
#pragma unroll
                    for (int mi = 0; mi < 2; mi++) {
                        mma16816(acc[mi][nb + 2 * q],     ah[mi], &bl4[q][0]);
                        mma16816(acc[mi][nb + 2 * q + 1], ah[mi], &bl4[q][2]);
                    }
#pragma unroll
                for (int q = 0; q < 2; q++)
#pragma unroll
                    for (int mi = 0; mi < 2; mi++) {
                        mma16816(acc[mi][nb + 2 * q],     al[mi], &bh4[q][0]);
                        mma16816(acc[mi][nb + 2 * q + 1], al[mi], &bh4[q][2]);
                    }
            }
        }
        __syncthreads();
    }

#pragma unroll
    for (int mi = 0; mi < 2; mi++) {
        int m = m0 + wm * 32 + mi * 16 + grp;
#pragma unroll
        for (int ni = 0; ni < 8; ni++) {
            int n = n0 + wn * 64 + ni * 8 + qd * 2;
            float b0 = bias[n], b1 = bias[n + 1];
            *(float2*)(Co + (size_t)m * ncols + n) =
                make_float2(acc[mi][ni][0] + b0, acc[mi][ni][1] + b1);
            *(float2*)(Co + (size_t)(m + 8) * ncols + n) =
                make_float2(acc[mi][ni][2] + b0, acc[mi][ni][3] + b1);
        }
    }
}

// ====== K4: sparse aggregate + per-row norm + relu; writes hi/lo bf16 h ======
__global__ __launch_bounds__(128) void combine_kernel(const float* __restrict__ X)
{
    const int row = blockIdx.x, tid = threadIdx.x;
    const int warp = tid >> 5, lane = tid & 31;
    __shared__ int   nidx[16];
    __shared__ float nw[16];
    __shared__ float wred[4];
    __shared__ float mean_s, inv_s;

    const int   deg = g_deg[row];
    const float di  = g_dinv[row];
    if (tid < deg) {
        int j = g_idx[row * 16 + tid];
        nidx[tid] = j;
        nw[tid]   = di * g_dinv[j];
    }
    __syncthreads();

    const int c = tid * 4;
    float4 a = *(const float4*)&g_u[(size_t)row * CH + c];
    for (int t = 0; t < deg; t++) {
        float4 vv = *(const float4*)&g_v[(size_t)nidx[t] * CH + c];
        float w = nw[t];
        a.x = fmaf(w, vv.x, a.x); a.y = fmaf(w, vv.y, a.y);
        a.z = fmaf(w, vv.z, a.z); a.w = fmaf(w, vv.w, a.w);
    }

    float s = a.x + a.y + a.z + a.w;
#pragma unroll
    for (int o = 16; o > 0; o >>= 1) s += __shfl_xor_sync(0xffffffffu, s, o);
    if (lane == 0) wred[warp] = s;
    __syncthreads();
    if (tid == 0) mean_s = (wred[0] + wred[1] + wred[2] + wred[3]) * (1.f / CH);
    __syncthreads();
    const float mean = mean_s;

    float d0 = a.x - mean, d1 = a.y - mean, d2 = a.z - mean, d3 = a.w - mean;
    float vs = d0 * d0 + d1 * d1 + d2 * d2 + d3 * d3;
#pragma unroll
    for (int o = 16; o > 0; o >>= 1) vs += __shfl_xor_sync(0xffffffffu, vs, o);
    if (lane == 0) wred[warp] = vs;
    __syncthreads();
    if (tid == 0) inv_s = rsqrtf((wred[0] + wred[1] + wred[2] + wred[3]) * (1.f / CH) + EPSV);
    __syncthreads();
    const float inv = inv_s;

    float4 xv = *(const float4*)&X[(size_t)row * CH + c];
    float h[4];
    h[0] = fmaxf(xv.x + d0 * inv, 0.f);
    h[1] = fmaxf(xv.y + d1 * inv, 0.f);
    h[2] = fmaxf(xv.z + d2 * inv, 0.f);
    h[3] = fmaxf(xv.w + d3 * inv, 0.f);

    uint32_t hw[2], lw[2];
#pragma unroll
    for (int p = 0; p < 2; p++) {
        __nv_bfloat16 b0 = __float2bfloat16_rn(h[p * 2]);
        __nv_bfloat16 b1 = __float2bfloat16_rn(h[p * 2 + 1]);
        __nv_bfloat162 hp; hp.x = b0; hp.y = b1;
        __nv_bfloat162 lp = __floats2bfloat162_rn(h[p * 2] - __bfloat162float(b0),
                                                  h[p * 2 + 1] - __bfloat162float(b1));
        hw[p] = *(uint32_t*)&hp;
        lw[p] = *(uint32_t*)&lp;
    }
    *(uint2*)&g_hh[(size_t)row * CH + c] = make_uint2(hw[0], hw[1]);
    *(uint2*)&g_hl[(size_t)row * CH + c] = make_uint2(lw[0], lw[1]);
}

// ---------------- one-time aux stream/events (host-side; no device mem alloc) ------
namespace {
struct Aux {
    cudaStream_t s1;
    cudaEvent_t  e_split, e_uv;
    Aux() {
        cudaStreamCreateWithFlags(&s1, cudaStreamNonBlocking);
        cudaEventCreateWithFlags(&e_split, cudaEventDisableTiming);
        cudaEventCreateWithFlags(&e_uv,    cudaEventDisableTiming);
    }
};
Aux g_aux;
}

// ================= launch: fork uv onto side stream, join before combine ===========
extern "C" void kernel_launch(void* const* d_in, const int* in_sizes, int n_in,
                              void* d_out, int out_size)
{
    const float* x  = (const float*)d_in[0];
    const float* Uw = (const float*)d_in[1];
    const float* Ub = (const float*)d_in[2];
    const float* Vw = (const float*)d_in[3];
    const float* Vb = (const float*)d_in[4];
    const float* Fw = (const float*)d_in[5];
    const float* Fb = (const float*)d_in[6];
    float* out = (float*)d_out;

    // main stream: split
    split_kernel<<<2688, 256>>>(x, Uw, Vw, Fw);
    cudaEventRecord(g_aux.e_split, 0);

    // side stream: fused u,v (tensor-bound) — overlaps si+topk branch
    cudaStreamWaitEvent(g_aux.s1, g_aux.e_split, 0);
    lin_mma<<<dim3(4, 32, 2), 256, 0, g_aux.s1>>>(Ub, Vb, nullptr, CH, 0);
    cudaEventRecord(g_aux.e_uv, g_aux.s1);

    // main stream: si + topk (depends on split only)
    si_mma<<<dim3(32, 32), 256>>>();
    topk_refine<<<NPTS, 256>>>(x);

    // join: combine needs topk (main) and uv (side)
    cudaStreamWaitEvent(0, g_aux.e_uv, 0);
    combine_kernel<<<NPTS, 128>>>(x);
    lin_mma<<<dim3(2, 32, 1), 256>>>(Fb, nullptr, out, OUTF, 2); // fc
}

// round 17
// speedup vs baseline: 1.2554x; 1.0261x over previous
#include <cuda_runtime.h>
#include <cuda_bf16.h>
#include <cstdint>

#define NPTS 4096
#define CH   512
#define OUTF 256
#define EPSV 1e-5f
#define SA   40   // smem k-stride (bf16): 80B rows -> conflict-free ldmatrix

// ---------------- scratch (device-side only) ----------------
__device__ __nv_bfloat16 g_sib[(size_t)NPTS * NPTS];
__device__ float g_u [(size_t)NPTS * CH];
__device__ float g_v [(size_t)NPTS * CH];
__device__ float g_dinv[NPTS];
__device__ int   g_deg [NPTS];
__device__ int   g_idx [NPTS * 16];
__device__ __nv_bfloat16 g_xh[(size_t)NPTS * CH], g_xl[(size_t)NPTS * CH];
__device__ __nv_bfloat16 g_uwh[CH * CH],  g_uwl[CH * CH];
__device__ __nv_bfloat16 g_vwh[CH * CH],  g_vwl[CH * CH];
__device__ __nv_bfloat16 g_fwh[OUTF * CH], g_fwl[OUTF * CH];
__device__ __nv_bfloat16 g_hh[(size_t)NPTS * CH], g_hl[(size_t)NPTS * CH];

__device__ __forceinline__ void mma16816(float c[4], const uint32_t a[4], const uint32_t b[2])
{
    asm volatile(
        "mma.sync.aligned.m16n8k16.row.col.f32.bf16.bf16.f32 "
        "{%0,%1,%2,%3}, {%4,%5,%6,%7}, {%8,%9}, {%0,%1,%2,%3};"
        : "+f"(c[0]), "+f"(c[1]), "+f"(c[2]), "+f"(c[3])
        : "r"(a[0]), "r"(a[1]), "r"(a[2]), "r"(a[3]), "r"(b[0]), "r"(b[1]));
}

__device__ __forceinline__ void ldsm_x4(uint32_t r[4], uint32_t saddr)
{
    asm volatile("ldmatrix.sync.aligned.m8n8.x4.shared.b16 {%0,%1,%2,%3}, [%4];"
                 : "=r"(r[0]), "=r"(r[1]), "=r"(r[2]), "=r"(r[3]) : "r"(saddr));
}

// ================= K0: one-shot hi/lo bf16 split of x, Uw, Vw, fc_w =================
__global__ __launch_bounds__(256) void split_kernel(const float* __restrict__ X,
                                                    const float* __restrict__ Uw,
                                                    const float* __restrict__ Vw,
                                                    const float* __restrict__ Fw)
{
    size_t i = (size_t)blockIdx.x * 256 + threadIdx.x;
    const float* src; __nv_bfloat16 *dh, *dl; size_t off;
    if (i < 524288)      { src = X;  dh = g_xh;  dl = g_xl;  off = i; }
    else if (i < 589824) { src = Uw; dh = g_uwh; dl = g_uwl; off = i - 524288; }
    else if (i < 655360) { src = Vw; dh = g_vwh; dl = g_vwl; off = i - 589824; }
    else                 { src = Fw; dh = g_fwh; dl = g_fwl; off = i - 655360; }

    float4 v = ((const float4*)src)[off];
    float f[4] = {v.x, v.y, v.z, v.w};
    uint32_t hw[2], lw[2];
#pragma unroll
    for (int p = 0; p < 2; p++) {
        __nv_bfloat16 h0 = __float2bfloat16_rn(f[p * 2]);
        __nv_bfloat16 h1 = __float2bfloat16_rn(f[p * 2 + 1]);
        __nv_bfloat162 hp; hp.x = h0; hp.y = h1;
        __nv_bfloat162 lp = __floats2bfloat162_rn(f[p * 2] - __bfloat162float(h0),
                                                  f[p * 2 + 1] - __bfloat162float(h1));
        hw[p] = *(uint32_t*)&hp;
        lw[p] = *(uint32_t*)&lp;
    }
    *(uint2*)&dh[off * 4] = make_uint2(hw[0], hw[1]);
    *(uint2*)&dl[off * 4] = make_uint2(lw[0], lw[1]);
}

// ===== K1: si = xh@xh.T, upper-tri blocks + smem-transposed mirror; ldmatrix =====
__global__ __launch_bounds__(256, 2) void si_mma()
{
    const int bj = blockIdx.x, bi = blockIdx.y;
    if (bi > bj) return;
    const int m0 = bi * 128, n0 = bj * 128;

    __shared__ __align__(16) unsigned char sraw[128 * 136 * 2];
    __nv_bfloat16* As = reinterpret_cast<__nv_bfloat16*>(sraw);
    __nv_bfloat16* Bs = As + 128 * SA;
    __nv_bfloat16* Ts = reinterpret_cast<__nv_bfloat16*>(sraw);

    const int tid  = threadIdx.x;
    const int warp = tid >> 5, lane = tid & 31;
    const int wm = warp & 3, wn = warp >> 2;
    const int grp = lane >> 2, qd = lane & 3;
    const int l7 = lane & 7;

    const uint32_t As_u = (uint32_t)__cvta_generic_to_shared(As);
    const uint32_t Bs_u = (uint32_t)__cvta_generic_to_shared(Bs);
    const uint32_t a_off = ((wm * 32 + ((lane >> 3) & 1) * 8 + l7) * SA + ((lane >> 4) & 1) * 8) * 2;
    const uint32_t b_off = ((wn * 64 + ((lane >> 4) & 1) * 8 + l7) * SA + ((lane >> 3) & 1) * 8) * 2;

    float acc[2][8][4];
#pragma unroll
    for (int mi = 0; mi < 2; mi++)
#pragma unroll
        for (int ni = 0; ni < 8; ni++)
#pragma unroll
            for (int e = 0; e < 4; e++) acc[mi][ni][e] = 0.f;

    const int ldr = tid >> 2;
    const int seg = (tid & 3) * 8;

    for (int k0 = 0; k0 < CH; k0 += 32) {
#pragma unroll
        for (int p = 0; p < 2; p++) {
            int rr = ldr + p * 64;
            *(uint4*)&As[rr * SA + seg] = *(const uint4*)&g_xh[(size_t)(m0 + rr) * CH + k0 + seg];
            *(uint4*)&Bs[rr * SA + seg] = *(const uint4*)&g_xh[(size_t)(n0 + rr) * CH + k0 + seg];
        }
        __syncthreads();
#pragma unroll
        for (int kk = 0; kk < 32; kk += 16) {
            uint32_t afr[2][4];
#pragma unroll
            for (int mi = 0; mi < 2; mi++)
                ldsm_x4(afr[mi], As_u + a_off + (mi * 16 * SA + kk) * 2);
#pragma unroll
            for (int ni = 0; ni < 8; ni += 2) {
                uint32_t b4[4];
                ldsm_x4(b4, Bs_u + b_off + (ni * 8 * SA + kk) * 2);
#pragma unroll
                for (int mi = 0; mi < 2; mi++) {
                    mma16816(acc[mi][ni],     afr[mi], &b4[0]);
                    mma16816(acc[mi][ni + 1], afr[mi], &b4[2]);
                }
            }
        }
        __syncthreads();
    }

#pragma unroll
    for (int mi = 0; mi < 2; mi++) {
        int m = m0 + wm * 32 + mi * 16 + grp;
#pragma unroll
        for (int ni = 0; ni < 8; ni++) {
            int n = n0 + wn * 64 + ni * 8 + qd * 2;
            *(__nv_bfloat162*)&g_sib[(size_t)m * NPTS + n] =
                __floats2bfloat162_rn(acc[mi][ni][0], acc[mi][ni][1]);
            *(__nv_bfloat162*)&g_sib[(size_t)(m + 8) * NPTS + n] =
                __floats2bfloat162_rn(acc[mi][ni][2], acc[mi][ni][3]);
        }
    }

    if (bi != bj) {
#pragma unroll
        for (int mi = 0; mi < 2; mi++) {
            int ml = wm * 32 + mi * 16 + grp;
#pragma unroll
            for (int ni = 0; ni < 8; ni++) {
                int nl = wn * 64 + ni * 8 + qd * 2;
                Ts[nl * 136 + ml]           = __float2bfloat16_rn(acc[mi][ni][0]);
                Ts[(nl + 1) * 136 + ml]     = __float2bfloat16_rn(acc[mi][ni][1]);
                Ts[nl * 136 + ml + 8]       = __float2bfloat16_rn(acc[mi][ni][2]);
                Ts[(nl + 1) * 136 + ml + 8] = __float2bfloat16_rn(acc[mi][ni][3]);
            }
        }
        __syncthreads();
        const int r = tid >> 1, hh = (tid & 1) * 64;
#pragma unroll
        for (int i = 0; i < 8; i++) {
            *(uint4*)&g_sib[(size_t)(n0 + r) * NPTS + m0 + hh + i * 8] =
                *(const uint4*)&Ts[r * 136 + hh + i * 8];
        }
    }
}

// ======= K2: hmax2-tree prescreen + approx top-4 (margin) + fp32 exact refine =======
__device__ __forceinline__ void ins4(float& v0, float& v1, float& v2, float& v3, float x)
{
    if (x > v3) {
        if (x > v1) {
            if (x > v0) { v3 = v2; v2 = v1; v1 = v0; v0 = x; }
            else        { v3 = v2; v2 = v1; v1 = x; }
        } else {
            if (x > v2) { v3 = v2; v2 = x; }
            else        { v3 = x; }
        }
    }
}

#define TOPK_MARGIN 4.0f

__global__ __launch_bounds__(256) void topk_refine(const float* __restrict__ X)
{
    const int row = blockIdx.x;
    const int tid = threadIdx.x;
    const int warp = tid >> 5, lane = tid & 31;
    const uint4* __restrict__ s4 = (const uint4*)(g_sib + (size_t)row * NPTS);

    __shared__ float xr[CH];
    __shared__ float wtop[8][4];
    __shared__ float ex[32];
    __shared__ int   cand[32];
    __shared__ int   cnt;
    __shared__ float thr_s;

    xr[tid]       = X[(size_t)row * CH + tid];
    xr[tid + 256] = X[(size_t)row * CH + tid + 256];
    if (tid == 0) cnt = 0;

    uint4 u0 = s4[tid];
    uint4 u1 = s4[tid + 256];
    __nv_bfloat162 p0 = __hmax2(*(__nv_bfloat162*)&u0.x, *(__nv_bfloat162*)&u0.y);
    __nv_bfloat162 p1 = __hmax2(*(__nv_bfloat162*)&u0.z, *(__nv_bfloat162*)&u0.w);
    __nv_bfloat162 p2 = __hmax2(*(__nv_bfloat162*)&u1.x, *(__nv_bfloat162*)&u1.y);
    __nv_bfloat162 p3 = __hmax2(*(__nv_bfloat162*)&u1.z, *(__nv_bfloat162*)&u1.w);
    __nv_bfloat162 pm = __hmax2(__hmax2(p0, p1), __hmax2(p2, p3));
    const float e = __bfloat162float(pm.x);
    const float o = __bfloat162float(pm.y);
    const float tmax = fmaxf(e, o);

    float v0 = tmax, v1 = fminf(e, o), v2 = -1e30f, v3 = -1e30f;
#pragma unroll
    for (int of = 16; of > 0; of >>= 1) {
        float o0 = __shfl_xor_sync(0xffffffffu, v0, of);
        float o1 = __shfl_xor_sync(0xffffffffu, v1, of);
        float o2 = __shfl_xor_sync(0xffffffffu, v2, of);
        float o3 = __shfl_xor_sync(0xffffffffu, v3, of);
        ins4(v0, v1, v2, v3, o0);
        ins4(v0, v1, v2, v3, o1);
        ins4(v0, v1, v2, v3, o2);
        ins4(v0, v1, v2, v3, o3);
    }
    if (lane == 0) { wtop[warp][0] = v0; wtop[warp][1] = v1; wtop[warp][2] = v2; wtop[warp][3] = v3; }
    __syncthreads();

    if (warp == 0) {
        float b0 = ((const float*)wtop)[lane];
        float w0 = b0, w1 = -1e30f, w2 = -1e30f, w3 = -1e30f;
#pragma unroll
        for (int of = 16; of > 0; of >>= 1) {
            float o0 = __shfl_xor_sync(0xffffffffu, w0, of);
            float o1 = __shfl_xor_sync(0xffffffffu, w1, of);
            float o2 = __shfl_xor_sync(0xffffffffu, w2, of);
            float o3 = __shfl_xor_sync(0xffffffffu, w3, of);
            ins4(w0, w1, w2, w3, o0);
            ins4(w0, w1, w2, w3, o1);
            ins4(w0, w1, w2, w3, o2);
            ins4(w0, w1, w2, w3, o3);
        }
        if (lane == 0) thr_s = w3 - TOPK_MARGIN;
    }
    __syncthreads();
    const float thr = thr_s;

    if (tmax >= thr) {
        uint32_t w[8] = {u0.x, u0.y, u0.z, u0.w, u1.x, u1.y, u1.z, u1.w};
#pragma unroll
        for (int t = 0; t < 8; t++) {
            __nv_bfloat162 p = *(__nv_bfloat162*)&w[t];
            int base = (t < 4 ? tid * 8 : (tid + 256) * 8 - 8) + t * 2;
            if (__bfloat162float(p.x) >= thr) {
                int pi = atomicAdd(&cnt, 1);
                if (pi < 32) cand[pi] = base;
            }
            if (__bfloat162float(p.y) >= thr) {
                int pi = atomicAdd(&cnt, 1);
                if (pi < 32) cand[pi] = base + 1;
            }
        }
    }
    __syncthreads();
    const int cn = min(cnt, 32);

    for (int c = warp; c < cn; c += 8) {
        const float* __restrict__ xc = X + (size_t)cand[c] * CH;
        float sum = 0.f;
        for (int k = lane; k < CH; k += 32) sum = fmaf(xr[k], xc[k], sum);
#pragma unroll
        for (int of = 16; of > 0; of >>= 1) sum += __shfl_xor_sync(0xffffffffu, sum, of);
        if (lane == 0) ex[c] = sum;
    }
    __syncthreads();

    if (tid == 0) {
        float tmp[32];
        for (int c = 0; c < cn; c++) tmp[c] = ex[c];
        float t4 = -1e30f;
        for (int p = 0; p < 4; p++) {
            int bidx = 0; float bv = -1e30f;
            for (int c = 0; c < cn; c++) if (tmp[c] > bv) { bv = tmp[c]; bidx = c; }
            t4 = bv; tmp[bidx] = -1e30f;
        }
        int d = 0;
        for (int c = 0; c < cn; c++) {
            if (ex[c] >= t4) { if (d < 16) g_idx[row * 16 + d] = cand[c]; d++; }
        }
        g_deg[row]  = min(d, 16);
        g_dinv[row] = rsqrtf((float)d);
    }
}

// ======== split-bf16 linear, templated M-tile (64*MI), ldmatrix, product-major ========
// mode 0: A = xh/xl; z=0 -> U -> g_u, z=1 -> V -> g_v.   mode 2: A = hh/hl -> Cout.
template <int MI>
__global__ __launch_bounds__(256, 2) void lin_mma(const float* __restrict__ ba,
                                                  const float* __restrict__ bb,
                                                  float* __restrict__ Cout,
                                                  int ncols, int mode, int yoff)
{
    const bool z1 = (mode == 0) && (blockIdx.z == 1);
    const __nv_bfloat16* __restrict__ Ahs = (mode == 2) ? g_hh : g_xh;
    const __nv_bfloat16* __restrict__ Als = (mode == 2) ? g_hl : g_xl;
    const __nv_bfloat16* __restrict__ Wh  = (mode == 2) ? g_fwh : (z1 ? g_vwh : g_uwh);
    const __nv_bfloat16* __restrict__ Wl  = (mode == 2) ? g_fwl : (z1 ? g_vwl : g_uwl);
    const float* __restrict__ bias = z1 ? bb : ba;
    float* __restrict__ Co = (mode == 0) ? (z1 ? g_v : g_u) : Cout;

    const int n0 = blockIdx.x * 128, m0 = (blockIdx.y + yoff) * (64 * MI);

    __shared__ __nv_bfloat16 Ah[64 * MI * SA], Al[64 * MI * SA];
    __shared__ __nv_bfloat16 Bh[128 * SA],     Bl[128 * SA];

    const int tid  = threadIdx.x;
    const int warp = tid >> 5, lane = tid & 31;
    const int wm = warp & 3, wn = warp >> 2;
    const int grp = lane >> 2, qd = lane & 3;
    const int l7 = lane & 7;

    const uint32_t Ah_u = (uint32_t)__cvta_generic_to_shared(Ah);
    const uint32_t Al_u = (uint32_t)__cvta_generic_to_shared(Al);
    const uint32_t Bh_u = (uint32_t)__cvta_generic_to_shared(Bh);
    const uint32_t Bl_u = (uint32_t)__cvta_generic_to_shared(Bl);
    const uint32_t a_off = ((wm * (16 * MI) + ((lane >> 3) & 1) * 8 + l7) * SA + ((lane >> 4) & 1) * 8) * 2;
    const uint32_t b_off = ((wn * 64 + ((lane >> 4) & 1) * 8 + l7) * SA + ((lane >> 3) & 1) * 8) * 2;

    float acc[MI][8][4];
#pragma unroll
    for (int mi = 0; mi < MI; mi++)
#pragma unroll
        for (int ni = 0; ni < 8; ni++)
#pragma unroll
            for (int e = 0; e < 4; e++) acc[mi][ni][e] = 0.f;

    const int ldr = tid >> 2;
    const int seg = (tid & 3) * 8;

    for (int k0 = 0; k0 < CH; k0 += 32) {
#pragma unroll
        for (int p = 0; p < MI; p++) {
            int rr = ldr + p * 64;
            *(uint4*)&Ah[rr * SA + seg] = *(const uint4*)&Ahs[(size_t)(m0 + rr) * CH + k0 + seg];
            *(uint4*)&Al[rr * SA + seg] = *(const uint4*)&Als[(size_t)(m0 + rr) * CH + k0 + seg];
        }
#pragma unroll
        for (int p = 0; p < 2; p++) {
            int rr = ldr + p * 64;
            *(uint4*)&Bh[rr * SA + seg] = *(const uint4*)&Wh[(size_t)(n0 + rr) * CH + k0 + seg];
            *(uint4*)&Bl[rr * SA + seg] = *(const uint4*)&Wl[(size_t)(n0 + rr) * CH + k0 + seg];
        }
        __syncthreads();
#pragma unroll
        for (int kk = 0; kk < 32; kk += 16) {
            uint32_t ah[MI][4], al[MI][4];
#pragma unroll
            for (int mi = 0; mi < MI; mi++) {
                ldsm_x4(ah[mi], Ah_u + a_off + (mi * 16 * SA + kk) * 2);
                ldsm_x4(al[mi], Al_u + a_off + (mi * 16 * SA + kk) * 2);
            }
#pragma unroll
            for (int nb = 0; nb < 8; nb += 4) {
                uint32_t bh4[2][4], bl4[2][4];
                ldsm_x4(bh4[0], Bh_u + b_off + (nb * 8 * SA + kk) * 2);
                ldsm_x4(bh4[1], Bh_u + b_off + ((nb + 2) * 8 * SA + kk) * 2);
                ldsm_x4(bl4[0], Bl_u + b_off + (nb * 8 * SA + kk) * 2);
                ldsm_x4(bl4[1], Bl_u + b_off + ((nb + 2) * 8 * SA + kk) * 2);
#pragma unroll
                for (int q = 0; q < 2; q++)
#pragma unroll
                    for (int mi = 0; mi < MI; mi++) {
                        mma16816(acc[mi][nb + 2 * q],     ah[mi], &bh4[q][0]);
                        mma16816(acc[mi][nb + 2 * q + 1], ah[mi], &bh4[q][2]);
                    }
#pragma unroll
                for (int q = 0; q < 2; q++)
#pragma unroll
                    for (int mi = 0; mi < MI; mi++) {
                        mma16816(acc[mi][nb + 2 * q],     ah[mi], &bl4[q][0]);
                        mma16816(acc[mi][nb + 2 * q + 1], ah[mi], &bl4[q][2]);
                    }
#pragma unroll
                for (int q = 0; q < 2; q++)
#pragma unroll
                    for (int mi = 0; mi < MI; mi++) {
                        mma16816(acc[mi][nb + 2 * q],     al[mi], &bh4[q][0]);
                        mma16816(acc[mi][nb + 2 * q + 1], al[mi], &bh4[q][2]);
                    }
            }
        }
        __syncthreads();
    }

#pragma unroll
    for (int mi = 0; mi < MI; mi++) {
        int m = m0 + wm * (16 * MI) + mi * 16 + grp;
#pragma unroll
        for (int ni = 0; ni < 8; ni++) {
            int n = n0 + wn * 64 + ni * 8 + qd * 2;
            float b0 = bias[n], b1 = bias[n + 1];
            *(float2*)(Co + (size_t)m * ncols + n) =
                make_float2(acc[mi][ni][0] + b0, acc[mi][ni][1] + b1);
            *(float2*)(Co + (size_t)(m + 8) * ncols + n) =
                make_float2(acc[mi][ni][2] + b0, acc[mi][ni][3] + b1);
        }
    }
}

// ====== K4: sparse aggregate + per-row norm + relu; writes hi/lo bf16 h ======
__global__ __launch_bounds__(128) void combine_kernel(const float* __restrict__ X, int row0)
{
    const int row = blockIdx.x + row0, tid = threadIdx.x;
    const int warp = tid >> 5, lane = tid & 31;
    __shared__ int   nidx[16];
    __shared__ float nw[16];
    __shared__ float wred[4];
    __shared__ float mean_s, inv_s;

    const int   deg = g_deg[row];
    const float di  = g_dinv[row];
    if (tid < deg) {
        int j = g_idx[row * 16 + tid];
        nidx[tid] = j;
        nw[tid]   = di * g_dinv[j];
    }
    __syncthreads();

    const int c = tid * 4;
    float4 a = *(const float4*)&g_u[(size_t)row * CH + c];
    for (int t = 0; t < deg; t++) {
        float4 vv = *(const float4*)&g_v[(size_t)nidx[t] * CH + c];
        float w = nw[t];
        a.x = fmaf(w, vv.x, a.x); a.y = fmaf(w, vv.y, a.y);
        a.z = fmaf(w, vv.z, a.z); a.w = fmaf(w, vv.w, a.w);
    }

    float s = a.x + a.y + a.z + a.w;
#pragma unroll
    for (int o = 16; o > 0; o >>= 1) s += __shfl_xor_sync(0xffffffffu, s, o);
    if (lane == 0) wred[warp] = s;
    __syncthreads();
    if (tid == 0) mean_s = (wred[0] + wred[1] + wred[2] + wred[3]) * (1.f / CH);
    __syncthreads();
    const float mean = mean_s;

    float d0 = a.x - mean, d1 = a.y - mean, d2 = a.z - mean, d3 = a.w - mean;
    float vs = d0 * d0 + d1 * d1 + d2 * d2 + d3 * d3;
#pragma unroll
    for (int o = 16; o > 0; o >>= 1) vs += __shfl_xor_sync(0xffffffffu, vs, o);
    if (lane == 0) wred[warp] = vs;
    __syncthreads();
    if (tid == 0) inv_s = rsqrtf((wred[0] + wred[1] + wred[2] + wred[3]) * (1.f / CH) + EPSV);
    __syncthreads();
    const float inv = inv_s;

    float4 xv = *(const float4*)&X[(size_t)row * CH + c];
    float h[4];
    h[0] = fmaxf(xv.x + d0 * inv, 0.f);
    h[1] = fmaxf(xv.y + d1 * inv, 0.f);
    h[2] = fmaxf(xv.z + d2 * inv, 0.f);
    h[3] = fmaxf(xv.w + d3 * inv, 0.f);

    uint32_t hw[2], lw[2];
#pragma unroll
    for (int p = 0; p < 2; p++) {
        __nv_bfloat16 b0 = __float2bfloat16_rn(h[p * 2]);
        __nv_bfloat16 b1 = __float2bfloat16_rn(h[p * 2 + 1]);
        __nv_bfloat162 hp; hp.x = b0; hp.y = b1;
        __nv_bfloat162 lp = __floats2bfloat162_rn(h[p * 2] - __bfloat162float(b0),
                                                  h[p * 2 + 1] - __bfloat162float(b1));
        hw[p] = *(uint32_t*)&hp;
        lw[p] = *(uint32_t*)&lp;
    }
    *(uint2*)&g_hh[(size_t)row * CH + c] = make_uint2(hw[0], hw[1]);
    *(uint2*)&g_hl[(size_t)row * CH + c] = make_uint2(lw[0], lw[1]);
}

// ---------------- one-time aux stream/events (host-side; no device mem alloc) ------
namespace {
struct Aux {
    cudaStream_t s1;
    cudaEvent_t  e_split, e_uv, e_c1, e_fc1;
    Aux() {
        cudaStreamCreateWithFlags(&s1, cudaStreamNonBlocking);
        cudaEventCreateWithFlags(&e_split, cudaEventDisableTiming);
        cudaEventCreateWithFlags(&e_uv,    cudaEventDisableTiming);
        cudaEventCreateWithFlags(&e_c1,    cudaEventDisableTiming);
        cudaEventCreateWithFlags(&e_fc1,   cudaEventDisableTiming);
    }
};
Aux g_aux;
}

// ====== launch: uv forked; combine halves AFTER full topk; fc_h1 overlaps combine_h2 ======
extern "C" void kernel_launch(void* const* d_in, const int* in_sizes, int n_in,
                              void* d_out, int out_size)
{
    const float* x  = (const float*)d_in[0];
    const float* Uw = (const float*)d_in[1];
    const float* Ub = (const float*)d_in[2];
    const float* Vw = (const float*)d_in[3];
    const float* Vb = (const float*)d_in[4];
    const float* Fw = (const float*)d_in[5];
    const float* Fb = (const float*)d_in[6];
    float* out = (float*)d_out;

    // main: split
    split_kernel<<<2688, 256>>>(x, Uw, Vw, Fw);
    cudaEventRecord(g_aux.e_split, 0);

    // side: fused u,v (overlaps si + topk)
    cudaStreamWaitEvent(g_aux.s1, g_aux.e_split, 0);
    lin_mma<2><<<dim3(4, 32, 2), 256, 0, g_aux.s1>>>(Ub, Vb, nullptr, CH, 0, 0);
    cudaEventRecord(g_aux.e_uv, g_aux.s1);

    // main: si + full topk (combine needs ALL rows' deg/dinv — cannot split topk before combine)
    si_mma<<<dim3(32, 32), 256>>>();
    topk_refine<<<NPTS, 256>>>(x);

    // main: combine half 1 (needs full topk + uv)
    cudaStreamWaitEvent(0, g_aux.e_uv, 0);
    combine_kernel<<<2048, 128>>>(x, 0);
    cudaEventRecord(g_aux.e_c1, 0);

    // side: fc half 1 (rows 0..2047 of h — self-contained) overlaps combine half 2
    cudaStreamWaitEvent(g_aux.s1, g_aux.e_c1, 0);
    lin_mma<1><<<dim3(2, 32, 1), 256, 0, g_aux.s1>>>(Fb, nullptr, out, OUTF, 2, 0);
    cudaEventRecord(g_aux.e_fc1, g_aux.s1);

    // main: combine half 2, then fc half 2
    combine_kernel<<<2048, 128>>>(x, 2048);
    lin_mma<1><<<dim3(2, 32, 1), 256>>>(Fb, nullptr, out, OUTF, 2, 32);

    // join side fork
    cudaStreamWaitEvent(0, g_aux.e_fc1, 0);
}